// round 1
// baseline (speedup 1.0000x reference)
#include <cuda_runtime.h>

#define Bv 64
#define Tv 24
#define Ev 256
#define Dv 25
#define Hv 625           // D*D
#define G4H 2500         // 4*H
#define G4D 100          // 4*D
#define XH_LD 1568       // padded row stride of xh
#define WO_LD 640        // padded row stride of wordOut (K padded from 625)
#define Vv 32000
#define NSTEP 23

// xh layout per batch row: [cU 0..24 | word 25..280 | cS 281..905 | hS 906..1530 | hU 1531..1555]
__device__ float g_xh[Bv * XH_LD];
__device__ float g_gS[Bv * G4H];
__device__ float g_bsumS[G4H];
__device__ float g_bsumU[G4D];
__device__ float g_wordOut[Tv * Bv * WO_LD];

__global__ void k_bsum(const float* __restrict__ bihS, const float* __restrict__ bhhS,
                       const float* __restrict__ bihU, const float* __restrict__ bhhU) {
    int i = blockIdx.x * blockDim.x + threadIdx.x;
    if (i < G4H) g_bsumS[i] = bihS[i] + bhhS[i];
    if (i < G4D) g_bsumU[i] = bihU[i] + bhhU[i];
}

// block b (64 blocks), 640 threads
__global__ void __launch_bounds__(640) k_init(
        const float* __restrict__ features, const float* __restrict__ embed,
        const float* __restrict__ szW, const float* __restrict__ szb) {
    int b = blockIdx.x;
    int t = threadIdx.x;
    __shared__ float s_f[Ev];
    if (t < Ev) s_f[t] = features[b * Ev + t];
    __syncthreads();
    float* xh = g_xh + b * XH_LD;
    if (t < Hv) {
        float acc = szb[t];
        const float* w = szW + t * Ev;
        #pragma unroll 4
        for (int k = 0; k < Ev; k++) acc += s_f[k] * w[k];
        xh[281 + t] = acc;    // cS = sStart
        xh[906 + t] = 0.f;    // hS = 0
    }
    if (t < Dv) {
        xh[t] = 0.f;          // cU = 0
        xh[1531 + t] = 0.f;   // hU = 0
    }
    if (t < Ev) xh[25 + t] = embed[t];   // word0 = embed_table[0]
    // zero wordOut row for t=0 (output[0] = fcb)
    g_wordOut[b * WO_LD + t] = 0.f;
}

// Generic tiled GEMM: C[M,N] = A[:, seg1]@W1^T + A[:, seg2]@W2^T + bias
template<int BM, int BN, int BK, int TM, int TN>
__global__ void __launch_bounds__((BM/TM)*(BN/TN)) gemm_tpl(
        const float* __restrict__ A, int lda,
        const float* __restrict__ W1, int ldw1, int K1, int aoff1,
        const float* __restrict__ W2, int ldw2, int K2, int aoff2,
        const float* __restrict__ bias,
        float* __restrict__ C, int ldc, int M, int N) {
    constexpr int THREADS = (BM/TM)*(BN/TN);
    __shared__ float As[BK][BM];
    __shared__ float Bs[BK][BN];
    const int tid = threadIdx.x;
    const int ntx = BN / TN;
    const int tn = (tid % ntx) * TN;
    const int tm = (tid / ntx) * TM;
    const int m0 = blockIdx.y * BM;
    const int n0 = blockIdx.x * BN;
    float acc[TM][TN];
    #pragma unroll
    for (int i = 0; i < TM; i++)
        #pragma unroll
        for (int j = 0; j < TN; j++) acc[i][j] = 0.f;

    #pragma unroll 1
    for (int seg = 0; seg < 2; seg++) {
        const float* W = seg ? W2 : W1;
        const int ldw = seg ? ldw2 : ldw1;
        const int K   = seg ? K2  : K1;
        const int aoff= seg ? aoff2 : aoff1;
        for (int k0 = 0; k0 < K; k0 += BK) {
            #pragma unroll
            for (int i = tid; i < BM*BK; i += THREADS) {
                int m = i / BK, k = i % BK;
                int gm = m0 + m, gk = k0 + k;
                As[k][m] = (gm < M && gk < K) ? A[gm * lda + aoff + gk] : 0.f;
            }
            #pragma unroll
            for (int i = tid; i < BN*BK; i += THREADS) {
                int n = i / BK, k = i % BK;
                int gn = n0 + n, gk = k0 + k;
                Bs[k][n] = (gn < N && gk < K) ? W[gn * ldw + gk] : 0.f;
            }
            __syncthreads();
            #pragma unroll
            for (int kk = 0; kk < BK; kk++) {
                float ra[TM], rb[TN];
                #pragma unroll
                for (int i = 0; i < TM; i++) ra[i] = As[kk][tm + i];
                #pragma unroll
                for (int j = 0; j < TN; j++) rb[j] = Bs[kk][tn + j];
                #pragma unroll
                for (int i = 0; i < TM; i++)
                    #pragma unroll
                    for (int j = 0; j < TN; j++)
                        acc[i][j] += ra[i] * rb[j];
            }
            __syncthreads();
        }
    }
    #pragma unroll
    for (int i = 0; i < TM; i++) {
        int gm = m0 + tm + i;
        if (gm >= M) continue;
        #pragma unroll
        for (int j = 0; j < TN; j++) {
            int gn = n0 + tn + j;
            if (gn < N) C[gm * ldc + gn] = acc[i][j] + bias[gn];
        }
    }
}

__device__ __forceinline__ float sigm(float x) { return 1.f / (1.f + expf(-x)); }

// block b (64 blocks), 640 threads. Does: lstmU gates, both cell updates,
// state rewrite into xh (incl. next word embedding), ut = hU@wuW^T+wub,
// ft = ut_mat @ hS_mat -> wordOut[step+1]
__global__ void __launch_bounds__(640) k_update_ft(
        const float* __restrict__ embed, const int* __restrict__ captions,
        const float* __restrict__ WihU, const float* __restrict__ WhhU,
        const float* __restrict__ wuW, const float* __restrict__ wub, int step) {
    int b = blockIdx.x;
    int t = threadIdx.x;
    __shared__ float s_x[906];
    __shared__ float s_hUo[Dv];
    __shared__ float s_gU[G4D];
    __shared__ float s_hS[Hv];
    __shared__ float s_hU[Dv];
    __shared__ float s_ut[Hv];
    float* xh = g_xh + b * XH_LD;
    for (int k = t; k < 906; k += 640) s_x[k] = xh[k];
    if (t < Dv) s_hUo[t] = xh[1531 + t];
    __syncthreads();

    // lstmU gates: gU[j] = x . WihU[j] + hU_old . WhhU[j] + bsumU[j]
    if (t < G4D) {
        float acc = g_bsumU[t];
        const float* w = WihU + t * 906;
        #pragma unroll 4
        for (int k = 0; k < 906; k++) acc += s_x[k] * w[k];
        const float* w2 = WhhU + t * Dv;
        #pragma unroll
        for (int k = 0; k < Dv; k++) acc += s_hUo[k] * w2[k];
        s_gU[t] = acc;
    }
    __syncthreads();

    // lstmS cell update (gate order i,f,g,o)
    if (t < Hv) {
        const float* gs = g_gS + b * G4H;
        float i = sigm(gs[t]);
        float f = sigm(gs[Hv + t]);
        float g = tanhf(gs[2*Hv + t]);
        float o = sigm(gs[3*Hv + t]);
        float c = f * s_x[281 + t] + i * g;
        float h = o * tanhf(c);
        s_hS[t] = h;
        xh[281 + t] = c;   // new cS
        xh[906 + t] = h;   // new hS
    }
    // lstmU cell update
    if (t < Dv) {
        float i = sigm(s_gU[t]);
        float f = sigm(s_gU[Dv + t]);
        float g = tanhf(s_gU[2*Dv + t]);
        float o = sigm(s_gU[3*Dv + t]);
        float c = f * s_x[t] + i * g;
        float h = o * tanhf(c);
        s_hU[t] = h;
        xh[t] = c;          // new cU
        xh[1531 + t] = h;   // new hU
    }
    // word embedding for next step (steps 1..22 use captions column s)
    if (step < NSTEP - 1 && t < Ev) {
        int w = captions[b * Tv + step + 1];
        xh[25 + t] = embed[w * Ev + t];
    }
    __syncthreads();

    // ut = hU @ wuW^T + wub  -> [625]
    if (t < Hv) {
        float acc = wub[t];
        const float* w = wuW + t * Dv;
        #pragma unroll
        for (int k = 0; k < Dv; k++) acc += s_hU[k] * w[k];
        s_ut[t] = acc;
    }
    __syncthreads();

    // ft[r*25+c] = sum_k ut[r][k] * hS[k][c]
    if (t < Hv) {
        int r = t / Dv, c = t % Dv;
        float acc = 0.f;
        #pragma unroll
        for (int k = 0; k < Dv; k++) acc += s_ut[r*Dv + k] * s_hS[k*Dv + c];
        g_wordOut[(size_t)(step + 1) * (Bv * WO_LD) + b * WO_LD + t] = acc;
    }
}

extern "C" void kernel_launch(void* const* d_in, const int* in_sizes, int n_in,
                              void* d_out, int out_size) {
    const float* features = (const float*)d_in[0];
    const int*   captions = (const int*)d_in[1];
    const float* embed    = (const float*)d_in[2];
    const float* WihS     = (const float*)d_in[3];
    const float* WhhS     = (const float*)d_in[4];
    const float* bihS     = (const float*)d_in[5];
    const float* bhhS     = (const float*)d_in[6];
    const float* WihU     = (const float*)d_in[7];
    const float* WhhU     = (const float*)d_in[8];
    const float* bihU     = (const float*)d_in[9];
    const float* bhhU     = (const float*)d_in[10];
    const float* fcW      = (const float*)d_in[11];
    const float* fcb      = (const float*)d_in[12];
    const float* szW      = (const float*)d_in[13];
    const float* szb      = (const float*)d_in[14];
    const float* wuW      = (const float*)d_in[15];
    const float* wub      = (const float*)d_in[16];
    float* out = (float*)d_out;

    float *p_xh, *p_gS, *p_wordOut, *p_bsumS;
    cudaGetSymbolAddress((void**)&p_xh, g_xh);
    cudaGetSymbolAddress((void**)&p_gS, g_gS);
    cudaGetSymbolAddress((void**)&p_wordOut, g_wordOut);
    cudaGetSymbolAddress((void**)&p_bsumS, g_bsumS);

    k_bsum<<<(G4H + 255) / 256, 256>>>(bihS, bhhS, bihU, bhhU);
    k_init<<<Bv, 640>>>(features, embed, szW, szb);

    for (int s = 0; s < NSTEP; s++) {
        // gS[64,2500] = xh[:,0:906]@WihS^T + xh[:,906:1531]@WhhS^T + bsum
        gemm_tpl<64,64,8,4,4><<<dim3((G4H + 63) / 64, 1), 256>>>(
            p_xh, XH_LD,
            WihS, 906, 906, 0,
            WhhS, Hv, Hv, 906,
            p_bsumS, p_gS, G4H, Bv, G4H);
        k_update_ft<<<Bv, 640>>>(embed, captions, WihU, WhhU, wuW, wub, s);
    }

    // out[1536, 32000] = wordOut[1536, 625] @ fcW^T + fcb
    gemm_tpl<128,128,8,8,8><<<dim3(Vv / 128, (Tv * Bv) / 128), 256>>>(
        p_wordOut, WO_LD,
        fcW, Hv, Hv, 0,
        fcW, Hv, 0, 0,
        fcb, out, Vv, Tv * Bv, Vv);
}

// round 4
// speedup vs baseline: 2.2425x; 2.2425x over previous
#include <cuda_runtime.h>

#define Bv 64
#define Tv 24
#define Ev 256
#define Dv 25
#define Hv 625           // D*D
#define G4H 2500         // 4*H
#define G4D 100          // 4*D
#define NC 2600          // combined gate rows (4H + 4D)
#define KC 1568          // combined K (1556 padded to 16)
#define XH_LD 1568       // padded row stride of xh
#define WO_LD 640        // padded row stride of wordOut
#define Vv 32000
#define NSTEP 23
#define SPLITK 7
#define KSEG 224         // KC / SPLITK, multiple of 16
#define UPD_T 768        // k_update threads (>= Hv + G4D = 725)

// xh layout per batch row: [cU 0..24 | word 25..280 | cS 281..905 | hS 906..1530 | hU 1531..1555 | pad..1567 (zero)]
__device__ float g_xh[Bv * XH_LD];
__device__ float g_Wc[NC * KC];          // combined gate weights  (~16.3 MB)
__device__ float g_bsumC[NC];
__device__ float g_gP[SPLITK * Bv * NC]; // split-K partials       (~4.7 MB)
__device__ float g_wordOut[Tv * Bv * WO_LD];

// ---------------------------------------------------------------------------
// Build combined weight matrix + bias sums (runs once per replay, ~16 MB write)
__global__ void __launch_bounds__(256) k_prep(
        const float* __restrict__ WihS, const float* __restrict__ WhhS,
        const float* __restrict__ bihS, const float* __restrict__ bhhS,
        const float* __restrict__ WihU, const float* __restrict__ WhhU,
        const float* __restrict__ bihU, const float* __restrict__ bhhU) {
    int j = blockIdx.x;
    float* w = g_Wc + (size_t)j * KC;
    if (j < G4H) {
        const float* wi = WihS + (size_t)j * 906;
        const float* wh = WhhS + (size_t)j * Hv;
        for (int k = threadIdx.x; k < KC; k += 256) {
            float v = 0.f;
            if (k < 906) v = wi[k];
            else if (k < 1531) v = wh[k - 906];
            w[k] = v;
        }
        if (threadIdx.x == 0) g_bsumC[j] = bihS[j] + bhhS[j];
    } else {
        int jj = j - G4H;
        const float* wi = WihU + (size_t)jj * 906;
        const float* wh = WhhU + (size_t)jj * Dv;
        for (int k = threadIdx.x; k < KC; k += 256) {
            float v = 0.f;
            if (k < 906) v = wi[k];
            else if (k >= 1531 && k < 1556) v = wh[k - 1531];
            w[k] = v;
        }
        if (threadIdx.x == 0) g_bsumC[j] = bihU[jj] + bhhU[jj];
    }
}

// ---------------------------------------------------------------------------
// Init state: sStart = features @ szW^T + szb; word0; zeros; wordOut[0] = 0
__global__ void __launch_bounds__(640) k_init(
        const float* __restrict__ features, const float* __restrict__ embed,
        const float* __restrict__ szW, const float* __restrict__ szb) {
    int b = blockIdx.x;
    int t = threadIdx.x;
    __shared__ float s_f[Ev];
    if (t < Ev) s_f[t] = features[b * Ev + t];
    __syncthreads();
    float* xh = g_xh + b * XH_LD;
    if (t < Hv) {
        float acc = szb[t];
        const float* w = szW + t * Ev;
        #pragma unroll 4
        for (int k = 0; k < Ev; k++) acc += s_f[k] * w[k];
        xh[281 + t] = acc;    // cS = sStart
        xh[906 + t] = 0.f;    // hS = 0
    }
    if (t < Dv) {
        xh[t] = 0.f;          // cU = 0
        xh[1531 + t] = 0.f;   // hU = 0
    }
    if (t < 12) xh[1556 + t] = 0.f;      // zero padding (part of GEMM K)
    if (t < Ev) xh[25 + t] = embed[t];   // word0 = embed_table[0]
    g_wordOut[b * WO_LD + t] = 0.f;      // output row t=0 is pure bias
}

// ---------------------------------------------------------------------------
// Gate GEMM, split-K: gP[z][b][n] = xh[b, z*224 : z*224+224] @ Wc[n, same]^T
// grid (41, 1, 7), 256 threads, BM=64 BN=64 BK=16 TM=4 TN=4
__global__ void __launch_bounds__(256) k_gates() {
    __shared__ float As[16][64];
    __shared__ float Bs[16][64];
    const int tid = threadIdx.x;
    const int tn = (tid % 16) * 4;
    const int tm = (tid / 16) * 4;
    const int n0 = blockIdx.x * 64;
    const int kbeg = blockIdx.z * KSEG;

    // load indices: each thread loads one float4 of A and of B per tile
    const int lm = tid / 4;            // 0..63
    const int lk = (tid % 4) * 4;      // 0,4,8,12
    const int gn = n0 + lm;
    const bool nok = gn < NC;
    const float* arow = g_xh + lm * XH_LD + kbeg + lk;
    const float* brow = nok ? (g_Wc + (size_t)gn * KC + kbeg + lk) : g_Wc;

    float acc[4][4];
    #pragma unroll
    for (int i = 0; i < 4; i++)
        #pragma unroll
        for (int j = 0; j < 4; j++) acc[i][j] = 0.f;

    for (int kt = 0; kt < KSEG / 16; kt++) {
        float4 a4 = *(const float4*)(arow + kt * 16);
        float4 b4 = nok ? *(const float4*)(brow + kt * 16)
                        : make_float4(0.f, 0.f, 0.f, 0.f);
        As[lk + 0][lm] = a4.x; As[lk + 1][lm] = a4.y;
        As[lk + 2][lm] = a4.z; As[lk + 3][lm] = a4.w;
        Bs[lk + 0][lm] = b4.x; Bs[lk + 1][lm] = b4.y;
        Bs[lk + 2][lm] = b4.z; Bs[lk + 3][lm] = b4.w;
        __syncthreads();
        #pragma unroll
        for (int kk = 0; kk < 16; kk++) {
            float ra[4], rb[4];
            #pragma unroll
            for (int i = 0; i < 4; i++) ra[i] = As[kk][tm + i];
            #pragma unroll
            for (int j = 0; j < 4; j++) rb[j] = Bs[kk][tn + j];
            #pragma unroll
            for (int i = 0; i < 4; i++)
                #pragma unroll
                for (int j = 0; j < 4; j++)
                    acc[i][j] += ra[i] * rb[j];
        }
        __syncthreads();
    }
    float* gp = g_gP + (size_t)blockIdx.z * (Bv * NC);
    #pragma unroll
    for (int i = 0; i < 4; i++) {
        int m = tm + i;                // batch row, always < 64
        #pragma unroll
        for (int j = 0; j < 4; j++) {
            int n = n0 + tn + j;
            if (n < NC) gp[m * NC + n] = acc[i][j];
        }
    }
}

__device__ __forceinline__ float sigm(float x) { return 1.f / (1.f + expf(-x)); }

// ---------------------------------------------------------------------------
// Reduce split-K partials, apply both LSTM cell updates, rewrite state,
// fetch next word embedding, compute ut and ft = ut_mat @ hS_mat
// 768 threads: t<625 -> lstmS, t in [625,725) -> lstmU gate reduction
__global__ void __launch_bounds__(UPD_T) k_update(
        const float* __restrict__ embed, const int* __restrict__ captions,
        const float* __restrict__ wuW, const float* __restrict__ wub, int step) {
    int b = blockIdx.x;
    int t = threadIdx.x;
    __shared__ float s_x[906];
    __shared__ float s_gU[G4D];
    __shared__ float s_hS[Hv];
    __shared__ float s_hU[Dv];
    __shared__ float s_ut[Hv];
    float* xh = g_xh + b * XH_LD;
    for (int k = t; k < 906; k += UPD_T) s_x[k] = xh[k];
    __syncthreads();

    if (t < Hv) {
        // lstmS: gather 4 gates across SPLITK partials (deterministic order)
        float g0 = g_bsumC[t];
        float g1 = g_bsumC[Hv + t];
        float g2 = g_bsumC[2 * Hv + t];
        float g3 = g_bsumC[3 * Hv + t];
        #pragma unroll
        for (int s = 0; s < SPLITK; s++) {
            const float* gp = g_gP + (size_t)(s * Bv + b) * NC;
            g0 += gp[t];
            g1 += gp[Hv + t];
            g2 += gp[2 * Hv + t];
            g3 += gp[3 * Hv + t];
        }
        float i = sigm(g0), f = sigm(g1), gg = tanhf(g2), o = sigm(g3);
        float c = f * s_x[281 + t] + i * gg;
        float h = o * tanhf(c);
        s_hS[t] = h;
        xh[281 + t] = c;   // new cS
        xh[906 + t] = h;   // new hS
    } else if (t < Hv + G4D) {
        int j = t - Hv;    // 0..99 (threads 625..724, block has 768)
        float g = g_bsumC[G4H + j];
        #pragma unroll
        for (int s = 0; s < SPLITK; s++)
            g += g_gP[(size_t)(s * Bv + b) * NC + G4H + j];
        s_gU[j] = g;
    }
    // next word embedding (steps 0..21 prepare words for steps 1..22)
    if (step < NSTEP - 1 && t < Ev) {
        int w = captions[b * Tv + step + 1];
        xh[25 + t] = embed[w * Ev + t];
    }
    __syncthreads();

    if (t < Dv) {
        float i = sigm(s_gU[t]);
        float f = sigm(s_gU[Dv + t]);
        float g = tanhf(s_gU[2 * Dv + t]);
        float o = sigm(s_gU[3 * Dv + t]);
        float c = f * s_x[t] + i * g;
        float h = o * tanhf(c);
        s_hU[t] = h;
        xh[t] = c;          // new cU
        xh[1531 + t] = h;   // new hU
    }
    __syncthreads();

    // ut = hU @ wuW^T + wub
    if (t < Hv) {
        float acc = wub[t];
        const float* w = wuW + t * Dv;
        #pragma unroll
        for (int k = 0; k < Dv; k++) acc += s_hU[k] * w[k];
        s_ut[t] = acc;
    }
    __syncthreads();

    // ft[r*25+c] = sum_k ut[r][k] * hS[k][c]
    if (t < Hv) {
        int r = t / Dv, c = t % Dv;
        float acc = 0.f;
        #pragma unroll
        for (int k = 0; k < Dv; k++) acc += s_ut[r * Dv + k] * s_hS[k * Dv + c];
        g_wordOut[(size_t)(step + 1) * (Bv * WO_LD) + b * WO_LD + t] = acc;
    }
}

// ---------------------------------------------------------------------------
// fc GEMM (unchanged control): C[M,N] = A @ W^T + bias, tiled SIMT
template<int BM, int BN, int BK, int TM, int TN>
__global__ void __launch_bounds__((BM/TM)*(BN/TN)) gemm_tpl(
        const float* __restrict__ A, int lda,
        const float* __restrict__ W1, int ldw1, int K1,
        const float* __restrict__ bias,
        float* __restrict__ C, int ldc, int M, int N) {
    constexpr int THREADS = (BM/TM)*(BN/TN);
    __shared__ float As[BK][BM];
    __shared__ float Bs[BK][BN];
    const int tid = threadIdx.x;
    const int ntx = BN / TN;
    const int tn = (tid % ntx) * TN;
    const int tm = (tid / ntx) * TM;
    const int m0 = blockIdx.y * BM;
    const int n0 = blockIdx.x * BN;
    float acc[TM][TN];
    #pragma unroll
    for (int i = 0; i < TM; i++)
        #pragma unroll
        for (int j = 0; j < TN; j++) acc[i][j] = 0.f;

    for (int k0 = 0; k0 < K1; k0 += BK) {
        #pragma unroll
        for (int i = tid; i < BM*BK; i += THREADS) {
            int m = i / BK, k = i % BK;
            int gm = m0 + m, gk = k0 + k;
            As[k][m] = (gm < M && gk < K1) ? A[gm * lda + gk] : 0.f;
        }
        #pragma unroll
        for (int i = tid; i < BN*BK; i += THREADS) {
            int n = i / BK, k = i % BK;
            int gn = n0 + n, gk = k0 + k;
            Bs[k][n] = (gn < N && gk < K1) ? W1[gn * ldw1 + gk] : 0.f;
        }
        __syncthreads();
        #pragma unroll
        for (int kk = 0; kk < BK; kk++) {
            float ra[TM], rb[TN];
            #pragma unroll
            for (int i = 0; i < TM; i++) ra[i] = As[kk][tm + i];
            #pragma unroll
            for (int j = 0; j < TN; j++) rb[j] = Bs[kk][tn + j];
            #pragma unroll
            for (int i = 0; i < TM; i++)
                #pragma unroll
                for (int j = 0; j < TN; j++)
                    acc[i][j] += ra[i] * rb[j];
        }
        __syncthreads();
    }
    #pragma unroll
    for (int i = 0; i < TM; i++) {
        int gm = m0 + tm + i;
        if (gm >= M) continue;
        #pragma unroll
        for (int j = 0; j < TN; j++) {
            int gn = n0 + tn + j;
            if (gn < N) C[gm * ldc + gn] = acc[i][j] + bias[gn];
        }
    }
}

extern "C" void kernel_launch(void* const* d_in, const int* in_sizes, int n_in,
                              void* d_out, int out_size) {
    const float* features = (const float*)d_in[0];
    const int*   captions = (const int*)d_in[1];
    const float* embed    = (const float*)d_in[2];
    const float* WihS     = (const float*)d_in[3];
    const float* WhhS     = (const float*)d_in[4];
    const float* bihS     = (const float*)d_in[5];
    const float* bhhS     = (const float*)d_in[6];
    const float* WihU     = (const float*)d_in[7];
    const float* WhhU     = (const float*)d_in[8];
    const float* bihU     = (const float*)d_in[9];
    const float* bhhU     = (const float*)d_in[10];
    const float* fcW      = (const float*)d_in[11];
    const float* fcb      = (const float*)d_in[12];
    const float* szW      = (const float*)d_in[13];
    const float* szb      = (const float*)d_in[14];
    const float* wuW      = (const float*)d_in[15];
    const float* wub      = (const float*)d_in[16];
    float* out = (float*)d_out;

    float *p_wordOut;
    cudaGetSymbolAddress((void**)&p_wordOut, g_wordOut);

    k_prep<<<NC, 256>>>(WihS, WhhS, bihS, bhhS, WihU, WhhU, bihU, bhhU);
    k_init<<<Bv, 640>>>(features, embed, szW, szb);

    for (int s = 0; s < NSTEP; s++) {
        k_gates<<<dim3((NC + 63) / 64, 1, SPLITK), 256>>>();
        k_update<<<Bv, UPD_T>>>(embed, captions, wuW, wub, s);
    }

    // out[1536, 32000] = wordOut[1536, 625] @ fcW^T + fcb
    gemm_tpl<128,128,8,8,8><<<dim3(Vv / 128, (Tv * Bv) / 128), 256>>>(
        p_wordOut, WO_LD, fcW, Hv, Hv, fcb, out, Vv, Tv * Bv, Vv);
}

// round 7
// speedup vs baseline: 4.0653x; 1.8128x over previous
#include <cuda_runtime.h>
#include <cuda_bf16.h>
#include <cstdint>

#define Bv 64
#define Tv 24
#define Ev 256
#define Dv 25
#define Hv 625           // D*D
#define G4H 2500         // 4*H
#define G4D 100          // 4*D
#define NC 2600          // combined gate rows (4H + 4D)
#define KC 1568          // combined K (1556 padded to 16)
#define XH_LD 1568       // padded row stride of xh
#define WO_LD 640        // padded row stride of wordOut
#define Vv 32000
#define NSTEP 23
#define SPLITK 7
#define KSEG 224         // KC / SPLITK
#define UPD_T 768        // k_update threads (>= Hv + G4D = 725)

// fc GEMM geometry (mma.sync bf16)
#define FCM 1536         // Tv*Bv
#define FCK 640          // 625 padded to 64-multiple
#define FC_BK 32
#define FC_NKT 20        // FCK / FC_BK per segment
#define FC_LDS 40        // padded SMEM row stride (bf16): 80 B, ldmatrix conflict-free

__device__ float g_xh[Bv * XH_LD];
__device__ float g_Wc[NC * KC];
__device__ float g_bsumC[NC];
__device__ float g_gP[SPLITK * Bv * NC];
__device__ float g_wordOut[Tv * Bv * WO_LD];
__device__ __nv_bfloat16 g_Wh[(size_t)Vv * FCK];
__device__ __nv_bfloat16 g_Wl[(size_t)Vv * FCK];
__device__ __nv_bfloat16 g_Ah[(size_t)FCM * FCK];
__device__ __nv_bfloat16 g_Al[(size_t)FCM * FCK];

// ---------------------------------------------------------------------------
__global__ void __launch_bounds__(256) k_prep(
        const float* __restrict__ WihS, const float* __restrict__ WhhS,
        const float* __restrict__ bihS, const float* __restrict__ bhhS,
        const float* __restrict__ WihU, const float* __restrict__ WhhU,
        const float* __restrict__ bihU, const float* __restrict__ bhhU) {
    int j = blockIdx.x;
    float* w = g_Wc + (size_t)j * KC;
    if (j < G4H) {
        const float* wi = WihS + (size_t)j * 906;
        const float* wh = WhhS + (size_t)j * Hv;
        for (int k = threadIdx.x; k < KC; k += 256) {
            float v = 0.f;
            if (k < 906) v = wi[k];
            else if (k < 1531) v = wh[k - 906];
            w[k] = v;
        }
        if (threadIdx.x == 0) g_bsumC[j] = bihS[j] + bhhS[j];
    } else {
        int jj = j - G4H;
        const float* wi = WihU + (size_t)jj * 906;
        const float* wh = WhhU + (size_t)jj * Dv;
        for (int k = threadIdx.x; k < KC; k += 256) {
            float v = 0.f;
            if (k < 906) v = wi[k];
            else if (k >= 1531 && k < 1556) v = wh[k - 1531];
            w[k] = v;
        }
        if (threadIdx.x == 0) g_bsumC[j] = bihU[jj] + bhhU[jj];
    }
}

// Split fcW (fp32 [V,625]) into hi/lo bf16 [V,640]
__global__ void __launch_bounds__(128) k_split_w(const float* __restrict__ fcW) {
    int row = blockIdx.x;
    const float* src = fcW + (size_t)row * Hv;
    __nv_bfloat16* dh = g_Wh + (size_t)row * FCK;
    __nv_bfloat16* dl = g_Wl + (size_t)row * FCK;
    for (int k = threadIdx.x; k < FCK; k += 128) {
        float x = (k < Hv) ? src[k] : 0.f;
        __nv_bfloat16 h = __float2bfloat16(x);
        float r = x - __bfloat162float(h);
        dh[k] = h;
        dl[k] = __float2bfloat16(r);
    }
}

// Split wordOut (fp32 [1536, WO_LD]) into hi/lo bf16 [1536,640]
__global__ void __launch_bounds__(128) k_split_a() {
    int row = blockIdx.x;
    const float* src = g_wordOut + (size_t)row * WO_LD;
    __nv_bfloat16* dh = g_Ah + (size_t)row * FCK;
    __nv_bfloat16* dl = g_Al + (size_t)row * FCK;
    for (int k = threadIdx.x; k < FCK; k += 128) {
        float x = (k < Hv) ? src[k] : 0.f;
        __nv_bfloat16 h = __float2bfloat16(x);
        float r = x - __bfloat162float(h);
        dh[k] = h;
        dl[k] = __float2bfloat16(r);
    }
}

// ---------------------------------------------------------------------------
__global__ void __launch_bounds__(640) k_init(
        const float* __restrict__ features, const float* __restrict__ embed,
        const float* __restrict__ szW, const float* __restrict__ szb) {
    int b = blockIdx.x;
    int t = threadIdx.x;
    __shared__ float s_f[Ev];
    if (t < Ev) s_f[t] = features[b * Ev + t];
    __syncthreads();
    float* xh = g_xh + b * XH_LD;
    if (t < Hv) {
        float acc = szb[t];
        const float* w = szW + t * Ev;
        #pragma unroll 4
        for (int k = 0; k < Ev; k++) acc += s_f[k] * w[k];
        xh[281 + t] = acc;
        xh[906 + t] = 0.f;
    }
    if (t < Dv) { xh[t] = 0.f; xh[1531 + t] = 0.f; }
    if (t < 12) xh[1556 + t] = 0.f;
    if (t < Ev) xh[25 + t] = embed[t];
    g_wordOut[b * WO_LD + t] = 0.f;      // row t=0 is pure bias
}

// ---------------------------------------------------------------------------
__global__ void __launch_bounds__(256) k_gates() {
    __shared__ float As[16][64];
    __shared__ float Bs[16][64];
    const int tid = threadIdx.x;
    const int tn = (tid % 16) * 4;
    const int tm = (tid / 16) * 4;
    const int n0 = blockIdx.x * 64;
    const int kbeg = blockIdx.z * KSEG;
    const int lm = tid / 4;
    const int lk = (tid % 4) * 4;
    const int gn = n0 + lm;
    const bool nok = gn < NC;
    const float* arow = g_xh + lm * XH_LD + kbeg + lk;
    const float* brow = nok ? (g_Wc + (size_t)gn * KC + kbeg + lk) : g_Wc;

    float acc[4][4];
    #pragma unroll
    for (int i = 0; i < 4; i++)
        #pragma unroll
        for (int j = 0; j < 4; j++) acc[i][j] = 0.f;

    for (int kt = 0; kt < KSEG / 16; kt++) {
        float4 a4 = *(const float4*)(arow + kt * 16);
        float4 b4 = nok ? *(const float4*)(brow + kt * 16)
                        : make_float4(0.f, 0.f, 0.f, 0.f);
        As[lk + 0][lm] = a4.x; As[lk + 1][lm] = a4.y;
        As[lk + 2][lm] = a4.z; As[lk + 3][lm] = a4.w;
        Bs[lk + 0][lm] = b4.x; Bs[lk + 1][lm] = b4.y;
        Bs[lk + 2][lm] = b4.z; Bs[lk + 3][lm] = b4.w;
        __syncthreads();
        #pragma unroll
        for (int kk = 0; kk < 16; kk++) {
            float ra[4], rb[4];
            #pragma unroll
            for (int i = 0; i < 4; i++) ra[i] = As[kk][tm + i];
            #pragma unroll
            for (int j = 0; j < 4; j++) rb[j] = Bs[kk][tn + j];
            #pragma unroll
            for (int i = 0; i < 4; i++)
                #pragma unroll
                for (int j = 0; j < 4; j++)
                    acc[i][j] += ra[i] * rb[j];
        }
        __syncthreads();
    }
    float* gp = g_gP + (size_t)blockIdx.z * (Bv * NC);
    #pragma unroll
    for (int i = 0; i < 4; i++) {
        int m = tm + i;
        #pragma unroll
        for (int j = 0; j < 4; j++) {
            int n = n0 + tn + j;
            if (n < NC) gp[m * NC + n] = acc[i][j];
        }
    }
}

__device__ __forceinline__ float sigm(float x) { return 1.f / (1.f + expf(-x)); }

// ---------------------------------------------------------------------------
__global__ void __launch_bounds__(UPD_T) k_update(
        const float* __restrict__ embed, const int* __restrict__ captions,
        const float* __restrict__ wuW, const float* __restrict__ wub, int step) {
    int b = blockIdx.x;
    int t = threadIdx.x;
    __shared__ float s_x[906];
    __shared__ float s_gU[G4D];
    __shared__ float s_hS[Hv];
    __shared__ float s_hU[Dv];
    __shared__ float s_ut[Hv];
    float* xh = g_xh + b * XH_LD;
    for (int k = t; k < 906; k += UPD_T) s_x[k] = xh[k];
    __syncthreads();

    if (t < Hv) {
        float g0 = g_bsumC[t];
        float g1 = g_bsumC[Hv + t];
        float g2 = g_bsumC[2 * Hv + t];
        float g3 = g_bsumC[3 * Hv + t];
        #pragma unroll
        for (int s = 0; s < SPLITK; s++) {
            const float* gp = g_gP + (size_t)(s * Bv + b) * NC;
            g0 += gp[t]; g1 += gp[Hv + t]; g2 += gp[2 * Hv + t]; g3 += gp[3 * Hv + t];
        }
        float i = sigm(g0), f = sigm(g1), gg = tanhf(g2), o = sigm(g3);
        float c = f * s_x[281 + t] + i * gg;
        float h = o * tanhf(c);
        s_hS[t] = h;
        xh[281 + t] = c;
        xh[906 + t] = h;
    } else if (t < Hv + G4D) {
        int j = t - Hv;
        float g = g_bsumC[G4H + j];
        #pragma unroll
        for (int s = 0; s < SPLITK; s++)
            g += g_gP[(size_t)(s * Bv + b) * NC + G4H + j];
        s_gU[j] = g;
    }
    if (step < NSTEP - 1 && t < Ev) {
        int w = captions[b * Tv + step + 1];
        xh[25 + t] = embed[w * Ev + t];
    }
    __syncthreads();

    if (t < Dv) {
        float i = sigm(s_gU[t]);
        float f = sigm(s_gU[Dv + t]);
        float g = tanhf(s_gU[2 * Dv + t]);
        float o = sigm(s_gU[3 * Dv + t]);
        float c = f * s_x[t] + i * g;
        float h = o * tanhf(c);
        s_hU[t] = h;
        xh[t] = c;
        xh[1531 + t] = h;
    }
    __syncthreads();

    if (t < Hv) {
        float acc = wub[t];
        const float* w = wuW + t * Dv;
        #pragma unroll
        for (int k = 0; k < Dv; k++) acc += s_hU[k] * w[k];
        s_ut[t] = acc;
    }
    __syncthreads();

    if (t < Hv) {
        int r = t / Dv, c = t % Dv;
        float acc = 0.f;
        #pragma unroll
        for (int k = 0; k < Dv; k++) acc += s_ut[r * Dv + k] * s_hS[k * Dv + c];
        g_wordOut[(size_t)(step + 1) * (Bv * WO_LD) + b * WO_LD + t] = acc;
    }
}

// ---------------------------------------------------------------------------
// fc GEMM: mma.sync bf16, C = Ah@Wh^T + Ah@Wl^T + Al@Wh^T + fcb
__device__ __forceinline__ uint32_t s2u(const void* p) {
    return (uint32_t)__cvta_generic_to_shared(p);
}
__device__ __forceinline__ void cp16(uint32_t dst, const void* src) {
    asm volatile("cp.async.cg.shared.global [%0], [%1], 16;\n" :: "r"(dst), "l"(src));
}
__device__ __forceinline__ void ldmA(uint32_t* a, uint32_t addr) {
    asm volatile("ldmatrix.sync.aligned.m8n8.x4.shared.b16 {%0,%1,%2,%3}, [%4];"
                 : "=r"(a[0]), "=r"(a[1]), "=r"(a[2]), "=r"(a[3]) : "r"(addr));
}
__device__ __forceinline__ void ldmB(uint32_t* b, uint32_t addr) {
    asm volatile("ldmatrix.sync.aligned.m8n8.x2.shared.b16 {%0,%1}, [%2];"
                 : "=r"(b[0]), "=r"(b[1]) : "r"(addr));
}
__device__ __forceinline__ void mma16816(float* c, const uint32_t* a, const uint32_t* b) {
    asm volatile(
        "mma.sync.aligned.m16n8k16.row.col.f32.bf16.bf16.f32 "
        "{%0,%1,%2,%3}, {%4,%5,%6,%7}, {%8,%9}, {%0,%1,%2,%3};"
        : "+f"(c[0]), "+f"(c[1]), "+f"(c[2]), "+f"(c[3])
        : "r"(a[0]), "r"(a[1]), "r"(a[2]), "r"(a[3]), "r"(b[0]), "r"(b[1]));
}

__global__ void __launch_bounds__(256) k_fc(const float* __restrict__ fcb,
                                            float* __restrict__ out) {
    __shared__ __align__(16) __nv_bfloat16 As[2][128][FC_LDS];
    __shared__ __align__(16) __nv_bfloat16 Bs[2][128][FC_LDS];

    const int tid = threadIdx.x;
    const int wid = tid / 32;
    const int lane = tid % 32;
    const int warp_m = wid / 4;        // 0..1 -> 64 rows
    const int warp_n = wid % 4;        // 0..3 -> 32 cols

    // patch swizzle: 10 patches of (12 M-tiles x 25 N-tiles) = 300 CTAs each
    int t = blockIdx.x;
    int patch = t / 300, within = t % 300;
    int m0 = (within % 12) * 128;
    int n0 = (patch * 25 + within / 12) * 128;

    const __nv_bfloat16* segA[3] = {
        g_Ah + (size_t)m0 * FCK, g_Ah + (size_t)m0 * FCK, g_Al + (size_t)m0 * FCK };
    const __nv_bfloat16* segW[3] = {
        g_Wh + (size_t)n0 * FCK, g_Wl + (size_t)n0 * FCK, g_Wh + (size_t)n0 * FCK };

    const int lr = tid >> 2;           // 0..63? no: 256/4 = 64 -> need 128 rows, 2 iters
    const int lc = tid & 3;            // 16B col group

    auto load = [&](int it, int stage) {
        int seg = it / FC_NKT, kt = it % FC_NKT;
        const __nv_bfloat16* A = segA[seg] + kt * FC_BK;
        const __nv_bfloat16* W = segW[seg] + kt * FC_BK;
        uint32_t sa = s2u(&As[stage][0][0]);
        uint32_t sbb = s2u(&Bs[stage][0][0]);
        #pragma unroll
        for (int i = 0; i < 2; i++) {
            int r = lr + i * 64;
            uint32_t soff = (r * FC_LDS + lc * 8) * 2;
            cp16(sa + soff, A + (size_t)r * FCK + lc * 8);
            cp16(sbb + soff, W + (size_t)r * FCK + lc * 8);
        }
        asm volatile("cp.async.commit_group;" ::: "memory");
    };

    float acc[4][4][4];
    #pragma unroll
    for (int i = 0; i < 4; i++)
        #pragma unroll
        for (int j = 0; j < 4; j++)
            #pragma unroll
            for (int q = 0; q < 4; q++) acc[i][j][q] = 0.f;

    // ldmatrix lane addressing
    const int agrp = lane >> 3;        // 0..3
    const int alr = lane & 7;
    const int am_off = (agrp & 1) * 8; // m offset within 16
    const int ak_off = (agrp >> 1) * 8;
    const int l16 = lane & 15;
    const int bn_off = l16 & 7;
    const int bk_off = (l16 >> 3) * 8;

    load(0, 0);
    const int NIT = 3 * FC_NKT;        // 60
    for (int it = 0; it < NIT; it++) {
        int s = it & 1;
        if (it + 1 < NIT) {
            load(it + 1, s ^ 1);
            asm volatile("cp.async.wait_group 1;" ::: "memory");
        } else {
            asm volatile("cp.async.wait_group 0;" ::: "memory");
        }
        __syncthreads();

        #pragma unroll
        for (int kf = 0; kf < 2; kf++) {
            uint32_t af[4][4], bf[4][2];
            #pragma unroll
            for (int mi = 0; mi < 4; mi++) {
                int row = warp_m * 64 + mi * 16 + am_off + alr;
                int col = kf * 16 + ak_off;
                ldmA(af[mi], s2u(&As[s][row][col]));
            }
            #pragma unroll
            for (int nj = 0; nj < 4; nj++) {
                int row = warp_n * 32 + nj * 8 + bn_off;
                int col = kf * 16 + bk_off;
                ldmB(bf[nj], s2u(&Bs[s][row][col]));
            }
            #pragma unroll
            for (int mi = 0; mi < 4; mi++)
                #pragma unroll
                for (int nj = 0; nj < 4; nj++)
                    mma16816(acc[mi][nj], af[mi], bf[nj]);
        }
        __syncthreads();
    }

    // epilogue: c0,c1 -> (m, n..n+1); c2,c3 -> (m+8, n..n+1)
    #pragma unroll
    for (int mi = 0; mi < 4; mi++) {
        int gm = m0 + warp_m * 64 + mi * 16 + lane / 4;
        #pragma unroll
        for (int nj = 0; nj < 4; nj++) {
            int gn = n0 + warp_n * 32 + nj * 8 + (lane % 4) * 2;
            float b0 = fcb[gn], b1 = fcb[gn + 1];
            float2 v0 = make_float2(acc[mi][nj][0] + b0, acc[mi][nj][1] + b1);
            float2 v1 = make_float2(acc[mi][nj][2] + b0, acc[mi][nj][3] + b1);
            *(float2*)(out + (size_t)gm * Vv + gn) = v0;
            *(float2*)(out + (size_t)(gm + 8) * Vv + gn) = v1;
        }
    }
}

// ---------------------------------------------------------------------------
extern "C" void kernel_launch(void* const* d_in, const int* in_sizes, int n_in,
                              void* d_out, int out_size) {
    const float* features = (const float*)d_in[0];
    const int*   captions = (const int*)d_in[1];
    const float* embed    = (const float*)d_in[2];
    const float* WihS     = (const float*)d_in[3];
    const float* WhhS     = (const float*)d_in[4];
    const float* bihS     = (const float*)d_in[5];
    const float* bhhS     = (const float*)d_in[6];
    const float* WihU     = (const float*)d_in[7];
    const float* WhhU     = (const float*)d_in[8];
    const float* bihU     = (const float*)d_in[9];
    const float* bhhU     = (const float*)d_in[10];
    const float* fcW      = (const float*)d_in[11];
    const float* fcb      = (const float*)d_in[12];
    const float* szW      = (const float*)d_in[13];
    const float* szb      = (const float*)d_in[14];
    const float* wuW      = (const float*)d_in[15];
    const float* wub      = (const float*)d_in[16];
    float* out = (float*)d_out;

    k_prep<<<NC, 256>>>(WihS, WhhS, bihS, bhhS, WihU, WhhU, bihU, bhhU);
    k_split_w<<<Vv, 128>>>(fcW);
    k_init<<<Bv, 640>>>(features, embed, szW, szb);

    for (int s = 0; s < NSTEP; s++) {
        k_gates<<<dim3((NC + 63) / 64, 1, SPLITK), 256>>>();
        k_update<<<Bv, UPD_T>>>(embed, captions, wuW, wub, s);
    }

    k_split_a<<<FCM, 128>>>();
    k_fc<<<(FCM / 128) * (Vv / 128), 256>>>(fcb, out);
}

// round 10
// speedup vs baseline: 4.3558x; 1.0715x over previous
#include <cuda_runtime.h>
#include <cuda_bf16.h>
#include <cstdint>

#define Bv 64
#define Tv 24
#define Ev 256
#define Dv 25
#define Hv 625           // D*D
#define G4H 2500         // 4*H
#define G4D 100          // 4*D
#define NC 2600          // combined gate rows (4H + 4D)
#define NCP 2688         // NC padded to 128-multiple
#define KC 1568          // combined K (1556 padded to 16)
#define XH_LD 1568       // padded row stride of xh
#define WO_LD 640        // padded row stride of wordOut
#define Vv 32000
#define NSTEP 23
#define SPLITK 7
#define KSEG 224         // KC / SPLITK
#define UPD_T 768        // k_update threads (>= Hv + G4D = 725)

// fc GEMM geometry (mma.sync bf16)
#define FCM 1536         // Tv*Bv
#define FCK 640          // 625 padded to 64-multiple
#define FC_BK 32
#define FC_NKT 20        // FCK / FC_BK per segment
#define FC_LDS 40        // padded SMEM row stride (bf16)

__device__ float g_xh[Bv * XH_LD];                  // fp32 master state
__device__ __nv_bfloat16 g_xh_h[Bv * XH_LD];        // bf16 hi copy
__device__ __nv_bfloat16 g_xh_l[Bv * XH_LD];        // bf16 lo copy
__device__ __nv_bfloat16 g_Wch[(size_t)NCP * KC];   // gate weights hi
__device__ __nv_bfloat16 g_Wcl[(size_t)NCP * KC];   // gate weights lo
__device__ float g_bsumC[NC];
__device__ float g_gP[(size_t)Bv * NCP * 8];        // split-K partials [b][n][8]
__device__ float g_wordOut[Tv * Bv * WO_LD];
__device__ __nv_bfloat16 g_Wh[(size_t)Vv * FCK];
__device__ __nv_bfloat16 g_Wl[(size_t)Vv * FCK];
__device__ __nv_bfloat16 g_Ah[(size_t)FCM * FCK];
__device__ __nv_bfloat16 g_Al[(size_t)FCM * FCK];

// ---------------------------------------------------------------------------
// Combined gate weights, split into bf16 hi/lo. Rows >= NC are zero.
__global__ void __launch_bounds__(256) k_prep(
        const float* __restrict__ WihS, const float* __restrict__ WhhS,
        const float* __restrict__ bihS, const float* __restrict__ bhhS,
        const float* __restrict__ WihU, const float* __restrict__ WhhU,
        const float* __restrict__ bihU, const float* __restrict__ bhhU) {
    int j = blockIdx.x;
    __nv_bfloat16* wh = g_Wch + (size_t)j * KC;
    __nv_bfloat16* wl = g_Wcl + (size_t)j * KC;
    for (int k = threadIdx.x; k < KC; k += 256) {
        float v = 0.f;
        if (j < G4H) {
            if (k < 906) v = WihS[(size_t)j * 906 + k];
            else if (k < 1531) v = WhhS[(size_t)j * Hv + (k - 906)];
        } else if (j < NC) {
            int jj = j - G4H;
            if (k < 906) v = WihU[(size_t)jj * 906 + k];
            else if (k >= 1531 && k < 1556) v = WhhU[(size_t)jj * Dv + (k - 1531)];
        }
        __nv_bfloat16 h = __float2bfloat16(v);
        wh[k] = h;
        wl[k] = __float2bfloat16(v - __bfloat162float(h));
    }
    if (threadIdx.x == 0 && j < NC) {
        g_bsumC[j] = (j < G4H) ? (bihS[j] + bhhS[j])
                               : (bihU[j - G4H] + bhhU[j - G4H]);
    }
}

// Split fcW (fp32 [V,625]) into hi/lo bf16 [V,640]
__global__ void __launch_bounds__(128) k_split_w(const float* __restrict__ fcW) {
    int row = blockIdx.x;
    const float* src = fcW + (size_t)row * Hv;
    __nv_bfloat16* dh = g_Wh + (size_t)row * FCK;
    __nv_bfloat16* dl = g_Wl + (size_t)row * FCK;
    for (int k = threadIdx.x; k < FCK; k += 128) {
        float x = (k < Hv) ? src[k] : 0.f;
        __nv_bfloat16 h = __float2bfloat16(x);
        dh[k] = h;
        dl[k] = __float2bfloat16(x - __bfloat162float(h));
    }
}

// Split wordOut into hi/lo bf16 [1536,640]
__global__ void __launch_bounds__(128) k_split_a() {
    int row = blockIdx.x;
    const float* src = g_wordOut + (size_t)row * WO_LD;
    __nv_bfloat16* dh = g_Ah + (size_t)row * FCK;
    __nv_bfloat16* dl = g_Al + (size_t)row * FCK;
    for (int k = threadIdx.x; k < FCK; k += 128) {
        float x = (k < Hv) ? src[k] : 0.f;
        __nv_bfloat16 h = __float2bfloat16(x);
        dh[k] = h;
        dl[k] = __float2bfloat16(x - __bfloat162float(h));
    }
}

// ---------------------------------------------------------------------------
__global__ void __launch_bounds__(640) k_init(
        const float* __restrict__ features, const float* __restrict__ embed,
        const float* __restrict__ szW, const float* __restrict__ szb) {
    int b = blockIdx.x;
    int t = threadIdx.x;
    __shared__ float s_f[Ev];
    if (t < Ev) s_f[t] = features[b * Ev + t];
    __syncthreads();
    float* xh = g_xh + b * XH_LD;
    if (t < Hv) {
        float acc = szb[t];
        const float* w = szW + t * Ev;
        #pragma unroll 4
        for (int k = 0; k < Ev; k++) acc += s_f[k] * w[k];
        xh[281 + t] = acc;
        xh[906 + t] = 0.f;
    }
    if (t < Dv) { xh[t] = 0.f; xh[1531 + t] = 0.f; }
    if (t < 12) xh[1556 + t] = 0.f;
    if (t < Ev) xh[25 + t] = embed[t];
    g_wordOut[b * WO_LD + t] = 0.f;
    __syncthreads();   // xh row complete -> build bf16 splits
    for (int k = t; k < XH_LD; k += 640) {
        float x = xh[k];
        __nv_bfloat16 h = __float2bfloat16(x);
        g_xh_h[b * XH_LD + k] = h;
        g_xh_l[b * XH_LD + k] = __float2bfloat16(x - __bfloat162float(h));
    }
}

// ---------------------------------------------------------------------------
// mma.sync helpers
__device__ __forceinline__ uint32_t s2u(const void* p) {
    return (uint32_t)__cvta_generic_to_shared(p);
}
__device__ __forceinline__ void cp16(uint32_t dst, const void* src) {
    asm volatile("cp.async.cg.shared.global [%0], [%1], 16;\n" :: "r"(dst), "l"(src));
}
__device__ __forceinline__ void ldmA(uint32_t* a, uint32_t addr) {
    asm volatile("ldmatrix.sync.aligned.m8n8.x4.shared.b16 {%0,%1,%2,%3}, [%4];"
                 : "=r"(a[0]), "=r"(a[1]), "=r"(a[2]), "=r"(a[3]) : "r"(addr));
}
__device__ __forceinline__ void ldmB(uint32_t* b, uint32_t addr) {
    asm volatile("ldmatrix.sync.aligned.m8n8.x2.shared.b16 {%0,%1}, [%2];"
                 : "=r"(b[0]), "=r"(b[1]) : "r"(addr));
}
__device__ __forceinline__ void mma16816(float* c, const uint32_t* a, const uint32_t* b) {
    asm volatile(
        "mma.sync.aligned.m16n8k16.row.col.f32.bf16.bf16.f32 "
        "{%0,%1,%2,%3}, {%4,%5,%6,%7}, {%8,%9}, {%0,%1,%2,%3};"
        : "+f"(c[0]), "+f"(c[1]), "+f"(c[2]), "+f"(c[3])
        : "r"(a[0]), "r"(a[1]), "r"(a[2]), "r"(a[3]), "r"(b[0]), "r"(b[1]));
}

// ---------------------------------------------------------------------------
// Gate GEMM (bf16 hi/lo, mma.sync, split-K over blockIdx.z)
// gP[b][n][z] = sum_products xh[b, seg] @ Wc[n, seg]^T
// grid (21, 1, 7), 128 threads (4 warps, warp = 64Mx32N)
#define G_LDS 40
__global__ void __launch_bounds__(128) k_gates() {
    __shared__ __align__(16) __nv_bfloat16 As[2][64][G_LDS];
    __shared__ __align__(16) __nv_bfloat16 Bs[2][128][G_LDS];

    const int tid = threadIdx.x;
    const int wid = tid / 32;          // warp_n
    const int lane = tid % 32;
    const int n0 = blockIdx.x * 128;
    const int z = blockIdx.z;
    const int kbeg = z * KSEG;

    const __nv_bfloat16* segA[3] = {
        g_xh_h + kbeg, g_xh_h + kbeg, g_xh_l + kbeg };
    const __nv_bfloat16* segW[3] = {
        g_Wch + (size_t)n0 * KC + kbeg, g_Wcl + (size_t)n0 * KC + kbeg,
        g_Wch + (size_t)n0 * KC + kbeg };

    const int lr = tid >> 2;           // 0..31
    const int lc = tid & 3;            // 16B column group (8 bf16)

    auto load = [&](int it, int stage) {
        int seg = it / 7, kt = it % 7;
        const __nv_bfloat16* A = segA[seg] + kt * 32;
        const __nv_bfloat16* W = segW[seg] + kt * 32;
        uint32_t sa = s2u(&As[stage][0][0]);
        uint32_t sbb = s2u(&Bs[stage][0][0]);
        #pragma unroll
        for (int i = 0; i < 2; i++) {
            int r = lr + i * 32;
            cp16(sa + (r * G_LDS + lc * 8) * 2, A + (size_t)r * XH_LD + lc * 8);
        }
        #pragma unroll
        for (int i = 0; i < 4; i++) {
            int r = lr + i * 32;
            cp16(sbb + (r * G_LDS + lc * 8) * 2, W + (size_t)r * KC + lc * 8);
        }
        asm volatile("cp.async.commit_group;" ::: "memory");
    };

    float acc[4][4][4];
    #pragma unroll
    for (int i = 0; i < 4; i++)
        #pragma unroll
        for (int j = 0; j < 4; j++)
            #pragma unroll
            for (int q = 0; q < 4; q++) acc[i][j][q] = 0.f;

    const int agrp = lane >> 3;
    const int alr = lane & 7;
    const int am_off = (agrp & 1) * 8;
    const int ak_off = (agrp >> 1) * 8;
    const int l16 = lane & 15;
    const int bn_off = l16 & 7;
    const int bk_off = (l16 >> 3) * 8;

    load(0, 0);
    const int NIT = 21;                // 3 products x 7 k-tiles
    for (int it = 0; it < NIT; it++) {
        int s = it & 1;
        if (it + 1 < NIT) {
            load(it + 1, s ^ 1);
            asm volatile("cp.async.wait_group 1;" ::: "memory");
        } else {
            asm volatile("cp.async.wait_group 0;" ::: "memory");
        }
        __syncthreads();

        #pragma unroll
        for (int kf = 0; kf < 2; kf++) {
            uint32_t af[4][4], bfr[4][2];
            #pragma unroll
            for (int mi = 0; mi < 4; mi++)
                ldmA(af[mi], s2u(&As[s][mi * 16 + am_off + alr][kf * 16 + ak_off]));
            #pragma unroll
            for (int nj = 0; nj < 4; nj++)
                ldmB(bfr[nj], s2u(&Bs[s][wid * 32 + nj * 8 + bn_off][kf * 16 + bk_off]));
            #pragma unroll
            for (int mi = 0; mi < 4; mi++)
                #pragma unroll
                for (int nj = 0; nj < 4; nj++)
                    mma16816(acc[mi][nj], af[mi], bfr[nj]);
        }
        __syncthreads();
    }

    // store partials: gP[(b*NCP + n)*8 + z]
    #pragma unroll
    for (int mi = 0; mi < 4; mi++) {
        int gm = mi * 16 + lane / 4;
        #pragma unroll
        for (int nj = 0; nj < 4; nj++) {
            int gn = n0 + wid * 32 + nj * 8 + (lane % 4) * 2;
            g_gP[((size_t)gm * NCP + gn) * 8 + z]       = acc[mi][nj][0];
            g_gP[((size_t)gm * NCP + gn + 1) * 8 + z]   = acc[mi][nj][1];
            g_gP[((size_t)(gm + 8) * NCP + gn) * 8 + z] = acc[mi][nj][2];
            g_gP[((size_t)(gm + 8) * NCP + gn + 1) * 8 + z] = acc[mi][nj][3];
        }
    }
}

__device__ __forceinline__ float sigm(float x) { return 1.f / (1.f + expf(-x)); }
__device__ __forceinline__ float red7(const float* p) {
    float4 u = *(const float4*)p;
    float4 v = *(const float4*)(p + 4);
    return u.x + u.y + u.z + u.w + v.x + v.y + v.z;   // 7 partials, slot 7 unused
}

// ---------------------------------------------------------------------------
__global__ void __launch_bounds__(UPD_T) k_update(
        const float* __restrict__ embed, const int* __restrict__ captions,
        const float* __restrict__ wuW, const float* __restrict__ wub, int step) {
    int b = blockIdx.x;
    int t = threadIdx.x;
    __shared__ float s_x[906];
    __shared__ float s_gU[G4D];
    __shared__ float s_hS[Hv];
    __shared__ float s_hU[Dv];
    __shared__ float s_ut[Hv];
    float* xh = g_xh + b * XH_LD;
    __nv_bfloat16* xhh = g_xh_h + b * XH_LD;
    __nv_bfloat16* xhl = g_xh_l + b * XH_LD;
    for (int k = t; k < 906; k += UPD_T) s_x[k] = xh[k];
    __syncthreads();

    const float* gpb = g_gP + (size_t)b * NCP * 8;
    if (t < Hv) {
        float g0 = g_bsumC[t]            + red7(gpb + (size_t)t * 8);
        float g1 = g_bsumC[Hv + t]       + red7(gpb + (size_t)(Hv + t) * 8);
        float g2 = g_bsumC[2 * Hv + t]   + red7(gpb + (size_t)(2 * Hv + t) * 8);
        float g3 = g_bsumC[3 * Hv + t]   + red7(gpb + (size_t)(3 * Hv + t) * 8);
        float i = sigm(g0), f = sigm(g1), gg = tanhf(g2), o = sigm(g3);
        float c = f * s_x[281 + t] + i * gg;
        float h = o * tanhf(c);
        s_hS[t] = h;
        xh[281 + t] = c;
        xh[906 + t] = h;
        __nv_bfloat16 ch = __float2bfloat16(c);
        xhh[281 + t] = ch;
        xhl[281 + t] = __float2bfloat16(c - __bfloat162float(ch));
        __nv_bfloat16 hh = __float2bfloat16(h);
        xhh[906 + t] = hh;
        xhl[906 + t] = __float2bfloat16(h - __bfloat162float(hh));
    } else if (t < Hv + G4D) {
        int j = t - Hv;
        s_gU[j] = g_bsumC[G4H + j] + red7(gpb + (size_t)(G4H + j) * 8);
    }
    if (step < NSTEP - 1 && t < Ev) {
        int w = captions[b * Tv + step + 1];
        float x = embed[w * Ev + t];
        xh[25 + t] = x;
        __nv_bfloat16 hh = __float2bfloat16(x);
        xhh[25 + t] = hh;
        xhl[25 + t] = __float2bfloat16(x - __bfloat162float(hh));
    }
    __syncthreads();

    if (t < Dv) {
        float i = sigm(s_gU[t]);
        float f = sigm(s_gU[Dv + t]);
        float g = tanhf(s_gU[2 * Dv + t]);
        float o = sigm(s_gU[3 * Dv + t]);
        float c = f * s_x[t] + i * g;
        float h = o * tanhf(c);
        s_hU[t] = h;
        xh[t] = c;
        xh[1531 + t] = h;
        __nv_bfloat16 ch = __float2bfloat16(c);
        xhh[t] = ch;
        xhl[t] = __float2bfloat16(c - __bfloat162float(ch));
        __nv_bfloat16 hh = __float2bfloat16(h);
        xhh[1531 + t] = hh;
        xhl[1531 + t] = __float2bfloat16(h - __bfloat162float(hh));
    }
    __syncthreads();

    if (t < Hv) {
        float acc = wub[t];
        const float* w = wuW + t * Dv;
        #pragma unroll
        for (int k = 0; k < Dv; k++) acc += s_hU[k] * w[k];
        s_ut[t] = acc;
    }
    __syncthreads();

    if (t < Hv) {
        int r = t / Dv, c = t % Dv;
        float acc = 0.f;
        #pragma unroll
        for (int k = 0; k < Dv; k++) acc += s_ut[r * Dv + k] * s_hS[k * Dv + c];
        g_wordOut[(size_t)(step + 1) * (Bv * WO_LD) + b * WO_LD + t] = acc;
    }
}

// ---------------------------------------------------------------------------
// fc GEMM (unchanged from R7)
__global__ void __launch_bounds__(256) k_fc(const float* __restrict__ fcb,
                                            float* __restrict__ out) {
    __shared__ __align__(16) __nv_bfloat16 As[2][128][FC_LDS];
    __shared__ __align__(16) __nv_bfloat16 Bs[2][128][FC_LDS];

    const int tid = threadIdx.x;
    const int wid = tid / 32;
    const int lane = tid % 32;
    const int warp_m = wid / 4;
    const int warp_n = wid % 4;

    int t = blockIdx.x;
    int patch = t / 300, within = t % 300;
    int m0 = (within % 12) * 128;
    int n0 = (patch * 25 + within / 12) * 128;

    const __nv_bfloat16* segA[3] = {
        g_Ah + (size_t)m0 * FCK, g_Ah + (size_t)m0 * FCK, g_Al + (size_t)m0 * FCK };
    const __nv_bfloat16* segW[3] = {
        g_Wh + (size_t)n0 * FCK, g_Wl + (size_t)n0 * FCK, g_Wh + (size_t)n0 * FCK };

    const int lr = tid >> 2;
    const int lc = tid & 3;

    auto load = [&](int it, int stage) {
        int seg = it / FC_NKT, kt = it % FC_NKT;
        const __nv_bfloat16* A = segA[seg] + kt * FC_BK;
        const __nv_bfloat16* W = segW[seg] + kt * FC_BK;
        uint32_t sa = s2u(&As[stage][0][0]);
        uint32_t sbb = s2u(&Bs[stage][0][0]);
        #pragma unroll
        for (int i = 0; i < 2; i++) {
            int r = lr + i * 64;
            uint32_t soff = (r * FC_LDS + lc * 8) * 2;
            cp16(sa + soff, A + (size_t)r * FCK + lc * 8);
            cp16(sbb + soff, W + (size_t)r * FCK + lc * 8);
        }
        asm volatile("cp.async.commit_group;" ::: "memory");
    };

    float acc[4][4][4];
    #pragma unroll
    for (int i = 0; i < 4; i++)
        #pragma unroll
        for (int j = 0; j < 4; j++)
            #pragma unroll
            for (int q = 0; q < 4; q++) acc[i][j][q] = 0.f;

    const int agrp = lane >> 3;
    const int alr = lane & 7;
    const int am_off = (agrp & 1) * 8;
    const int ak_off = (agrp >> 1) * 8;
    const int l16 = lane & 15;
    const int bn_off = l16 & 7;
    const int bk_off = (l16 >> 3) * 8;

    load(0, 0);
    const int NIT = 3 * FC_NKT;
    for (int it = 0; it < NIT; it++) {
        int s = it & 1;
        if (it + 1 < NIT) {
            load(it + 1, s ^ 1);
            asm volatile("cp.async.wait_group 1;" ::: "memory");
        } else {
            asm volatile("cp.async.wait_group 0;" ::: "memory");
        }
        __syncthreads();

        #pragma unroll
        for (int kf = 0; kf < 2; kf++) {
            uint32_t af[4][4], bfr[4][2];
            #pragma unroll
            for (int mi = 0; mi < 4; mi++) {
                int row = warp_m * 64 + mi * 16 + am_off + alr;
                ldmA(af[mi], s2u(&As[s][row][kf * 16 + ak_off]));
            }
            #pragma unroll
            for (int nj = 0; nj < 4; nj++) {
                int row = warp_n * 32 + nj * 8 + bn_off;
                ldmB(bfr[nj], s2u(&Bs[s][row][kf * 16 + bk_off]));
            }
            #pragma unroll
            for (int mi = 0; mi < 4; mi++)
                #pragma unroll
                for (int nj = 0; nj < 4; nj++)
                    mma16816(acc[mi][nj], af[mi], bfr[nj]);
        }
        __syncthreads();
    }

    #pragma unroll
    for (int mi = 0; mi < 4; mi++) {
        int gm = m0 + warp_m * 64 + mi * 16 + lane / 4;
        #pragma unroll
        for (int nj = 0; nj < 4; nj++) {
            int gn = n0 + warp_n * 32 + nj * 8 + (lane % 4) * 2;
            float b0 = fcb[gn], b1 = fcb[gn + 1];
            float2 v0 = make_float2(acc[mi][nj][0] + b0, acc[mi][nj][1] + b1);
            float2 v1 = make_float2(acc[mi][nj][2] + b0, acc[mi][nj][3] + b1);
            *(float2*)(out + (size_t)gm * Vv + gn) = v0;
            *(float2*)(out + (size_t)(gm + 8) * Vv + gn) = v1;
        }
    }
}

// ---------------------------------------------------------------------------
extern "C" void kernel_launch(void* const* d_in, const int* in_sizes, int n_in,
                              void* d_out, int out_size) {
    const float* features = (const float*)d_in[0];
    const int*   captions = (const int*)d_in[1];
    const float* embed    = (const float*)d_in[2];
    const float* WihS     = (const float*)d_in[3];
    const float* WhhS     = (const float*)d_in[4];
    const float* bihS     = (const float*)d_in[5];
    const float* bhhS     = (const float*)d_in[6];
    const float* WihU     = (const float*)d_in[7];
    const float* WhhU     = (const float*)d_in[8];
    const float* bihU     = (const float*)d_in[9];
    const float* bhhU     = (const float*)d_in[10];
    const float* fcW      = (const float*)d_in[11];
    const float* fcb      = (const float*)d_in[12];
    const float* szW      = (const float*)d_in[13];
    const float* szb      = (const float*)d_in[14];
    const float* wuW      = (const float*)d_in[15];
    const float* wub      = (const float*)d_in[16];
    float* out = (float*)d_out;

    k_prep<<<NCP, 256>>>(WihS, WhhS, bihS, bhhS, WihU, WhhU, bihU, bhhU);
    k_split_w<<<Vv, 128>>>(fcW);
    k_init<<<Bv, 640>>>(features, embed, szW, szb);

    for (int s = 0; s < NSTEP; s++) {
        k_gates<<<dim3(NCP / 128, 1, SPLITK), 128>>>();
        k_update<<<Bv, UPD_T>>>(embed, captions, wuW, wub, s);
    }

    k_split_a<<<FCM, 128>>>();
    k_fc<<<(FCM / 128) * (Vv / 128), 256>>>(fcb, out);
}

// round 11
// speedup vs baseline: 4.5083x; 1.0350x over previous
#include <cuda_runtime.h>
#include <cuda_bf16.h>
#include <cstdint>

#define Bv 64
#define Tv 24
#define Ev 256
#define Dv 25
#define Hv 625           // D*D
#define G4H 2500         // 4*H
#define G4D 100          // 4*D
#define NC 2600          // combined gate rows (4H + 4D)
#define NCP 2688         // NC padded to 128-multiple
#define KC 1568          // combined K (1556 padded to 16)
#define XH_LD 1568       // padded row stride of xh
#define WO_LD 640        // padded row stride of wordOut
#define Vv 32000
#define NSTEP 23
#define SPLITK 7
#define KSEG 224         // KC / SPLITK
#define UPD_T 768        // k_update threads (>= Hv + G4D = 725)

// fc GEMM geometry (mma.sync bf16)
#define FCM 1536         // Tv*Bv
#define FCK 640          // 625 padded to 64-multiple
#define FC_BK 32
#define FC_NKT 20        // FCK / FC_BK per segment
#define FC_LDS 40        // padded SMEM row stride (bf16)

__device__ float g_xh[Bv * XH_LD];                  // fp32 master state
__device__ __nv_bfloat16 g_xh_h[Bv * XH_LD];        // bf16 hi copy
__device__ __nv_bfloat16 g_xh_l[Bv * XH_LD];        // bf16 lo copy
__device__ __nv_bfloat16 g_Wch[(size_t)NCP * KC];   // gate weights hi
__device__ __nv_bfloat16 g_Wcl[(size_t)NCP * KC];   // gate weights lo
__device__ float g_bsumC[NC];
__device__ float g_gP[(size_t)Bv * NCP * 8];        // split-K partials [b][n][8]
__device__ float g_wordOut[Tv * Bv * WO_LD];
__device__ __nv_bfloat16 g_Wh[(size_t)Vv * FCK];
__device__ __nv_bfloat16 g_Wl[(size_t)Vv * FCK];
__device__ __nv_bfloat16 g_Ah[(size_t)FCM * FCK];
__device__ __nv_bfloat16 g_Al[(size_t)FCM * FCK];

// ---------------------------------------------------------------------------
// Combined gate weights, split into bf16 hi/lo. Rows >= NC are zero.
__global__ void __launch_bounds__(256) k_prep(
        const float* __restrict__ WihS, const float* __restrict__ WhhS,
        const float* __restrict__ bihS, const float* __restrict__ bhhS,
        const float* __restrict__ WihU, const float* __restrict__ WhhU,
        const float* __restrict__ bihU, const float* __restrict__ bhhU) {
    int j = blockIdx.x;
    __nv_bfloat16* wh = g_Wch + (size_t)j * KC;
    __nv_bfloat16* wl = g_Wcl + (size_t)j * KC;
    for (int k = threadIdx.x; k < KC; k += 256) {
        float v = 0.f;
        if (j < G4H) {
            if (k < 906) v = WihS[(size_t)j * 906 + k];
            else if (k < 1531) v = WhhS[(size_t)j * Hv + (k - 906)];
        } else if (j < NC) {
            int jj = j - G4H;
            if (k < 906) v = WihU[(size_t)jj * 906 + k];
            else if (k >= 1531 && k < 1556) v = WhhU[(size_t)jj * Dv + (k - 1531)];
        }
        __nv_bfloat16 h = __float2bfloat16(v);
        wh[k] = h;
        wl[k] = __float2bfloat16(v - __bfloat162float(h));
    }
    if (threadIdx.x == 0 && j < NC) {
        g_bsumC[j] = (j < G4H) ? (bihS[j] + bhhS[j])
                               : (bihU[j - G4H] + bhhU[j - G4H]);
    }
}

// Split fcW (fp32 [V,625]) into hi/lo bf16 [V,640]
__global__ void __launch_bounds__(128) k_split_w(const float* __restrict__ fcW) {
    int row = blockIdx.x;
    const float* src = fcW + (size_t)row * Hv;
    __nv_bfloat16* dh = g_Wh + (size_t)row * FCK;
    __nv_bfloat16* dl = g_Wl + (size_t)row * FCK;
    for (int k = threadIdx.x; k < FCK; k += 128) {
        float x = (k < Hv) ? src[k] : 0.f;
        __nv_bfloat16 h = __float2bfloat16(x);
        dh[k] = h;
        dl[k] = __float2bfloat16(x - __bfloat162float(h));
    }
}

// Split wordOut into hi/lo bf16 [1536,640]
__global__ void __launch_bounds__(128) k_split_a() {
    int row = blockIdx.x;
    const float* src = g_wordOut + (size_t)row * WO_LD;
    __nv_bfloat16* dh = g_Ah + (size_t)row * FCK;
    __nv_bfloat16* dl = g_Al + (size_t)row * FCK;
    for (int k = threadIdx.x; k < FCK; k += 128) {
        float x = (k < Hv) ? src[k] : 0.f;
        __nv_bfloat16 h = __float2bfloat16(x);
        dh[k] = h;
        dl[k] = __float2bfloat16(x - __bfloat162float(h));
    }
}

// ---------------------------------------------------------------------------
__global__ void __launch_bounds__(640) k_init(
        const float* __restrict__ features, const float* __restrict__ embed,
        const float* __restrict__ szW, const float* __restrict__ szb) {
    int b = blockIdx.x;
    int t = threadIdx.x;
    __shared__ float s_f[Ev];
    if (t < Ev) s_f[t] = features[b * Ev + t];
    __syncthreads();
    float* xh = g_xh + b * XH_LD;
    if (t < Hv) {
        float acc = szb[t];
        const float* w = szW + t * Ev;
        #pragma unroll 4
        for (int k = 0; k < Ev; k++) acc += s_f[k] * w[k];
        xh[281 + t] = acc;
        xh[906 + t] = 0.f;
    }
    if (t < Dv) { xh[t] = 0.f; xh[1531 + t] = 0.f; }
    if (t < 12) xh[1556 + t] = 0.f;
    if (t < Ev) xh[25 + t] = embed[t];
    g_wordOut[b * WO_LD + t] = 0.f;
    __syncthreads();   // xh row complete -> build bf16 splits
    for (int k = t; k < XH_LD; k += 640) {
        float x = xh[k];
        __nv_bfloat16 h = __float2bfloat16(x);
        g_xh_h[b * XH_LD + k] = h;
        g_xh_l[b * XH_LD + k] = __float2bfloat16(x - __bfloat162float(h));
    }
}

// ---------------------------------------------------------------------------
// mma.sync helpers
__device__ __forceinline__ uint32_t s2u(const void* p) {
    return (uint32_t)__cvta_generic_to_shared(p);
}
__device__ __forceinline__ void cp16(uint32_t dst, const void* src) {
    asm volatile("cp.async.cg.shared.global [%0], [%1], 16;\n" :: "r"(dst), "l"(src));
}
__device__ __forceinline__ void ldmA(uint32_t* a, uint32_t addr) {
    asm volatile("ldmatrix.sync.aligned.m8n8.x4.shared.b16 {%0,%1,%2,%3}, [%4];"
                 : "=r"(a[0]), "=r"(a[1]), "=r"(a[2]), "=r"(a[3]) : "r"(addr));
}
__device__ __forceinline__ void ldmB(uint32_t* b, uint32_t addr) {
    asm volatile("ldmatrix.sync.aligned.m8n8.x2.shared.b16 {%0,%1}, [%2];"
                 : "=r"(b[0]), "=r"(b[1]) : "r"(addr));
}
__device__ __forceinline__ void mma16816(float* c, const uint32_t* a, const uint32_t* b) {
    asm volatile(
        "mma.sync.aligned.m16n8k16.row.col.f32.bf16.bf16.f32 "
        "{%0,%1,%2,%3}, {%4,%5,%6,%7}, {%8,%9}, {%0,%1,%2,%3};"
        : "+f"(c[0]), "+f"(c[1]), "+f"(c[2]), "+f"(c[3])
        : "r"(a[0]), "r"(a[1]), "r"(a[2]), "r"(a[3]), "r"(b[0]), "r"(b[1]));
}

// ---------------------------------------------------------------------------
// Gate GEMM (bf16 hi/lo, mma.sync, split-K over blockIdx.z)
// grid (21, 1, 7), 256 threads (8 warps, warp = 32Mx32N), 4-stage pipeline
#define G_LDS 40
#define G_STG 4
#define G_NIT 21          // 3 products x 7 k-tiles
__global__ void __launch_bounds__(256) k_gates() {
    __shared__ __align__(16) __nv_bfloat16 As[G_STG][64][G_LDS];
    __shared__ __align__(16) __nv_bfloat16 Bs[G_STG][128][G_LDS];

    const int tid = threadIdx.x;
    const int wid = tid / 32;
    const int lane = tid % 32;
    const int warp_m = wid / 4;        // 0..1 -> 32 rows each
    const int warp_n = wid % 4;        // 0..3 -> 32 cols each
    const int n0 = blockIdx.x * 128;
    const int z = blockIdx.z;
    const int kbeg = z * KSEG;

    const __nv_bfloat16* segA[3] = {
        g_xh_h + kbeg, g_xh_h + kbeg, g_xh_l + kbeg };
    const __nv_bfloat16* segW[3] = {
        g_Wch + (size_t)n0 * KC + kbeg, g_Wcl + (size_t)n0 * KC + kbeg,
        g_Wch + (size_t)n0 * KC + kbeg };

    const int lr = tid >> 2;           // 0..63
    const int lc = tid & 3;            // 16B column group (8 bf16)

    // load k-tile `j` (wrapped) into pipeline stage `stage`
    auto load = [&](int j, int stage) {
        if (j >= G_NIT) j -= G_NIT;    // redundant tail load (keeps waits uniform)
        int seg = j / 7, kt = j % 7;
        const __nv_bfloat16* A = segA[seg] + kt * 32;
        const __nv_bfloat16* W = segW[seg] + kt * 32;
        uint32_t sa = s2u(&As[stage][0][0]);
        uint32_t sbb = s2u(&Bs[stage][0][0]);
        cp16(sa + (lr * G_LDS + lc * 8) * 2, A + (size_t)lr * XH_LD + lc * 8);
        #pragma unroll
        for (int i = 0; i < 2; i++) {
            int r = lr + i * 64;
            cp16(sbb + (r * G_LDS + lc * 8) * 2, W + (size_t)r * KC + lc * 8);
        }
        asm volatile("cp.async.commit_group;" ::: "memory");
    };

    float acc[2][4][4];
    #pragma unroll
    for (int i = 0; i < 2; i++)
        #pragma unroll
        for (int j = 0; j < 4; j++)
            #pragma unroll
            for (int q = 0; q < 4; q++) acc[i][j][q] = 0.f;

    const int agrp = lane >> 3;
    const int alr = lane & 7;
    const int am_off = (agrp & 1) * 8;
    const int ak_off = (agrp >> 1) * 8;
    const int l16 = lane & 15;
    const int bn_off = l16 & 7;
    const int bk_off = (l16 >> 3) * 8;

    load(0, 0); load(1, 1); load(2, 2); load(3, 3);

    for (int it = 0; it < G_NIT; it++) {
        int s = it & 3;
        asm volatile("cp.async.wait_group 3;" ::: "memory");  // stage `it` complete
        __syncthreads();

        #pragma unroll
        for (int kf = 0; kf < 2; kf++) {
            uint32_t af[2][4], bfr[4][2];
            #pragma unroll
            for (int mi = 0; mi < 2; mi++)
                ldmA(af[mi], s2u(&As[s][warp_m * 32 + mi * 16 + am_off + alr][kf * 16 + ak_off]));
            #pragma unroll
            for (int nj = 0; nj < 4; nj++)
                ldmB(bfr[nj], s2u(&Bs[s][warp_n * 32 + nj * 8 + bn_off][kf * 16 + bk_off]));
            #pragma unroll
            for (int mi = 0; mi < 2; mi++)
                #pragma unroll
                for (int nj = 0; nj < 4; nj++)
                    mma16816(acc[mi][nj], af[mi], bfr[nj]);
        }
        __syncthreads();                 // all warps done with stage s
        load(it + 4, s);                 // refill freed stage (wrapped past end)
    }

    // store partials: gP[(b*NCP + n)*8 + z]
    #pragma unroll
    for (int mi = 0; mi < 2; mi++) {
        int gm = warp_m * 32 + mi * 16 + lane / 4;
        #pragma unroll
        for (int nj = 0; nj < 4; nj++) {
            int gn = n0 + warp_n * 32 + nj * 8 + (lane % 4) * 2;
            g_gP[((size_t)gm * NCP + gn) * 8 + z]           = acc[mi][nj][0];
            g_gP[((size_t)gm * NCP + gn + 1) * 8 + z]       = acc[mi][nj][1];
            g_gP[((size_t)(gm + 8) * NCP + gn) * 8 + z]     = acc[mi][nj][2];
            g_gP[((size_t)(gm + 8) * NCP + gn + 1) * 8 + z] = acc[mi][nj][3];
        }
    }
}

__device__ __forceinline__ float sigm(float x) { return 1.f / (1.f + expf(-x)); }
__device__ __forceinline__ float red7(const float* p) {
    float4 u = *(const float4*)p;
    float4 v = *(const float4*)(p + 4);
    return u.x + u.y + u.z + u.w + v.x + v.y + v.z;   // 7 partials, slot 7 unused
}

// ---------------------------------------------------------------------------
__global__ void __launch_bounds__(UPD_T) k_update(
        const float* __restrict__ embed, const int* __restrict__ captions,
        const float* __restrict__ wuW, const float* __restrict__ wub, int step) {
    int b = blockIdx.x;
    int t = threadIdx.x;
    __shared__ float s_x[906];
    __shared__ float s_gU[G4D];
    __shared__ float s_hS[Hv];
    __shared__ float s_hU[Dv];
    __shared__ float s_ut[Hv];
    float* xh = g_xh + b * XH_LD;
    __nv_bfloat16* xhh = g_xh_h + b * XH_LD;
    __nv_bfloat16* xhl = g_xh_l + b * XH_LD;
    for (int k = t; k < 906; k += UPD_T) s_x[k] = xh[k];
    __syncthreads();

    const float* gpb = g_gP + (size_t)b * NCP * 8;
    if (t < Hv) {
        float g0 = g_bsumC[t]            + red7(gpb + (size_t)t * 8);
        float g1 = g_bsumC[Hv + t]       + red7(gpb + (size_t)(Hv + t) * 8);
        float g2 = g_bsumC[2 * Hv + t]   + red7(gpb + (size_t)(2 * Hv + t) * 8);
        float g3 = g_bsumC[3 * Hv + t]   + red7(gpb + (size_t)(3 * Hv + t) * 8);
        float i = sigm(g0), f = sigm(g1), gg = tanhf(g2), o = sigm(g3);
        float c = f * s_x[281 + t] + i * gg;
        float h = o * tanhf(c);
        s_hS[t] = h;
        xh[281 + t] = c;
        xh[906 + t] = h;
        __nv_bfloat16 ch = __float2bfloat16(c);
        xhh[281 + t] = ch;
        xhl[281 + t] = __float2bfloat16(c - __bfloat162float(ch));
        __nv_bfloat16 hh = __float2bfloat16(h);
        xhh[906 + t] = hh;
        xhl[906 + t] = __float2bfloat16(h - __bfloat162float(hh));
    } else if (t < Hv + G4D) {
        int j = t - Hv;
        s_gU[j] = g_bsumC[G4H + j] + red7(gpb + (size_t)(G4H + j) * 8);
    }
    if (step < NSTEP - 1 && t < Ev) {
        int w = captions[b * Tv + step + 1];
        float x = embed[w * Ev + t];
        xh[25 + t] = x;
        __nv_bfloat16 hh = __float2bfloat16(x);
        xhh[25 + t] = hh;
        xhl[25 + t] = __float2bfloat16(x - __bfloat162float(hh));
    }
    __syncthreads();

    if (t < Dv) {
        float i = sigm(s_gU[t]);
        float f = sigm(s_gU[Dv + t]);
        float g = tanhf(s_gU[2 * Dv + t]);
        float o = sigm(s_gU[3 * Dv + t]);
        float c = f * s_x[t] + i * g;
        float h = o * tanhf(c);
        s_hU[t] = h;
        xh[t] = c;
        xh[1531 + t] = h;
        __nv_bfloat16 ch = __float2bfloat16(c);
        xhh[t] = ch;
        xhl[t] = __float2bfloat16(c - __bfloat162float(ch));
        __nv_bfloat16 hh = __float2bfloat16(h);
        xhh[1531 + t] = hh;
        xhl[1531 + t] = __float2bfloat16(h - __bfloat162float(hh));
    }
    __syncthreads();

    if (t < Hv) {
        float acc = wub[t];
        const float* w = wuW + t * Dv;
        #pragma unroll
        for (int k = 0; k < Dv; k++) acc += s_hU[k] * w[k];
        s_ut[t] = acc;
    }
    __syncthreads();

    if (t < Hv) {
        int r = t / Dv, c = t % Dv;
        float acc = 0.f;
        #pragma unroll
        for (int k = 0; k < Dv; k++) acc += s_ut[r * Dv + k] * s_hS[k * Dv + c];
        g_wordOut[(size_t)(step + 1) * (Bv * WO_LD) + b * WO_LD + t] = acc;
    }
}

// ---------------------------------------------------------------------------
// fc GEMM (unchanged from R7)
__global__ void __launch_bounds__(256) k_fc(const float* __restrict__ fcb,
                                            float* __restrict__ out) {
    __shared__ __align__(16) __nv_bfloat16 As[2][128][FC_LDS];
    __shared__ __align__(16) __nv_bfloat16 Bs[2][128][FC_LDS];

    const int tid = threadIdx.x;
    const int wid = tid / 32;
    const int lane = tid % 32;
    const int warp_m = wid / 4;
    const int warp_n = wid % 4;

    int t = blockIdx.x;
    int patch = t / 300, within = t % 300;
    int m0 = (within % 12) * 128;
    int n0 = (patch * 25 + within / 12) * 128;

    const __nv_bfloat16* segA[3] = {
        g_Ah + (size_t)m0 * FCK, g_Ah + (size_t)m0 * FCK, g_Al + (size_t)m0 * FCK };
    const __nv_bfloat16* segW[3] = {
        g_Wh + (size_t)n0 * FCK, g_Wl + (size_t)n0 * FCK, g_Wh + (size_t)n0 * FCK };

    const int lr = tid >> 2;
    const int lc = tid & 3;

    auto load = [&](int it, int stage) {
        int seg = it / FC_NKT, kt = it % FC_NKT;
        const __nv_bfloat16* A = segA[seg] + kt * FC_BK;
        const __nv_bfloat16* W = segW[seg] + kt * FC_BK;
        uint32_t sa = s2u(&As[stage][0][0]);
        uint32_t sbb = s2u(&Bs[stage][0][0]);
        #pragma unroll
        for (int i = 0; i < 2; i++) {
            int r = lr + i * 64;
            uint32_t soff = (r * FC_LDS + lc * 8) * 2;
            cp16(sa + soff, A + (size_t)r * FCK + lc * 8);
            cp16(sbb + soff, W + (size_t)r * FCK + lc * 8);
        }
        asm volatile("cp.async.commit_group;" ::: "memory");
    };

    float acc[4][4][4];
    #pragma unroll
    for (int i = 0; i < 4; i++)
        #pragma unroll
        for (int j = 0; j < 4; j++)
            #pragma unroll
            for (int q = 0; q < 4; q++) acc[i][j][q] = 0.f;

    const int agrp = lane >> 3;
    const int alr = lane & 7;
    const int am_off = (agrp & 1) * 8;
    const int ak_off = (agrp >> 1) * 8;
    const int l16 = lane & 15;
    const int bn_off = l16 & 7;
    const int bk_off = (l16 >> 3) * 8;

    load(0, 0);
    const int NIT = 3 * FC_NKT;
    for (int it = 0; it < NIT; it++) {
        int s = it & 1;
        if (it + 1 < NIT) {
            load(it + 1, s ^ 1);
            asm volatile("cp.async.wait_group 1;" ::: "memory");
        } else {
            asm volatile("cp.async.wait_group 0;" ::: "memory");
        }
        __syncthreads();

        #pragma unroll
        for (int kf = 0; kf < 2; kf++) {
            uint32_t af[4][4], bfr[4][2];
            #pragma unroll
            for (int mi = 0; mi < 4; mi++) {
                int row = warp_m * 64 + mi * 16 + am_off + alr;
                ldmA(af[mi], s2u(&As[s][row][kf * 16 + ak_off]));
            }
            #pragma unroll
            for (int nj = 0; nj < 4; nj++) {
                int row = warp_n * 32 + nj * 8 + bn_off;
                ldmB(bfr[nj], s2u(&Bs[s][row][kf * 16 + bk_off]));
            }
            #pragma unroll
            for (int mi = 0; mi < 4; mi++)
                #pragma unroll
                for (int nj = 0; nj < 4; nj++)
                    mma16816(acc[mi][nj], af[mi], bfr[nj]);
        }
        __syncthreads();
    }

    #pragma unroll
    for (int mi = 0; mi < 4; mi++) {
        int gm = m0 + warp_m * 64 + mi * 16 + lane / 4;
        #pragma unroll
        for (int nj = 0; nj < 4; nj++) {
            int gn = n0 + warp_n * 32 + nj * 8 + (lane % 4) * 2;
            float b0 = fcb[gn], b1 = fcb[gn + 1];
            float2 v0 = make_float2(acc[mi][nj][0] + b0, acc[mi][nj][1] + b1);
            float2 v1 = make_float2(acc[mi][nj][2] + b0, acc[mi][nj][3] + b1);
            *(float2*)(out + (size_t)gm * Vv + gn) = v0;
            *(float2*)(out + (size_t)(gm + 8) * Vv + gn) = v1;
        }
    }
}

// ---------------------------------------------------------------------------
extern "C" void kernel_launch(void* const* d_in, const int* in_sizes, int n_in,
                              void* d_out, int out_size) {
    const float* features = (const float*)d_in[0];
    const int*   captions = (const int*)d_in[1];
    const float* embed    = (const float*)d_in[2];
    const float* WihS     = (const float*)d_in[3];
    const float* WhhS     = (const float*)d_in[4];
    const float* bihS     = (const float*)d_in[5];
    const float* bhhS     = (const float*)d_in[6];
    const float* WihU     = (const float*)d_in[7];
    const float* WhhU     = (const float*)d_in[8];
    const float* bihU     = (const float*)d_in[9];
    const float* bhhU     = (const float*)d_in[10];
    const float* fcW      = (const float*)d_in[11];
    const float* fcb      = (const float*)d_in[12];
    const float* szW      = (const float*)d_in[13];
    const float* szb      = (const float*)d_in[14];
    const float* wuW      = (const float*)d_in[15];
    const float* wub      = (const float*)d_in[16];
    float* out = (float*)d_out;

    k_split_w<<<Vv, 128>>>(fcW);    // big streaming writes first (keep Wc warm in L2)
    k_prep<<<NCP, 256>>>(WihS, WhhS, bihS, bhhS, WihU, WhhU, bihU, bhhU);
    k_init<<<Bv, 640>>>(features, embed, szW, szb);

    for (int s = 0; s < NSTEP; s++) {
        k_gates<<<dim3(NCP / 128, 1, SPLITK), 256>>>();
        k_update<<<Bv, UPD_T>>>(embed, captions, wuW, wub, s);
    }

    k_split_a<<<FCM, 128>>>();
    k_fc<<<(FCM / 128) * (Vv / 128), 256>>>(fcb, out);
}

// round 17
// speedup vs baseline: 4.5605x; 1.0116x over previous
#include <cuda_runtime.h>
#include <cuda_bf16.h>
#include <cstdint>

#define Bv 64
#define Tv 24
#define Ev 256
#define Dv 25
#define Hv 625           // D*D
#define G4H 2500         // 4*H
#define G4D 100          // 4*D
#define NC 2600          // combined gate rows (4H + 4D)
#define NCP 2688         // NC padded to 128-multiple
#define KC 1568          // combined K (1556 padded to 16)
#define XH_LD 1568       // padded row stride of xh
#define WO_LD 640        // padded row stride of wordOut
#define Vv 32000
#define NSTEP 23
#define SPLITK 7
#define KSEG 224         // KC / SPLITK
#define UPD_T 768        // k_update threads (>= Hv + G4D = 725)

// fc GEMM geometry (mma.sync bf16)
#define FCM 1536         // Tv*Bv
#define FCK 640          // 625 padded to 64-multiple
#define FC_BK 32
#define FC_NKT 20        // FCK / FC_BK per segment
#define FC_LDS 40        // padded SMEM row stride (bf16)

__device__ float g_xh[Bv * XH_LD];                  // fp32 master state
__device__ __nv_bfloat16 g_xh_h[Bv * XH_LD];        // bf16 hi copy
__device__ __nv_bfloat16 g_xh_l[Bv * XH_LD];        // bf16 lo copy
__device__ __nv_bfloat16 g_Wch[(size_t)NCP * KC];   // gate weights hi
__device__ __nv_bfloat16 g_Wcl[(size_t)NCP * KC];   // gate weights lo
__device__ float g_bsumC[NC];
__device__ float g_gP[(size_t)Bv * NCP * 8];        // split-K partials [b][n][8]
__device__ float g_wordOut[Tv * Bv * WO_LD];
__device__ __nv_bfloat16 g_Wh[(size_t)Vv * FCK];
__device__ __nv_bfloat16 g_Wl[(size_t)Vv * FCK];
__device__ __nv_bfloat16 g_Ah[(size_t)FCM * FCK];
__device__ __nv_bfloat16 g_Al[(size_t)FCM * FCK];

// ---------------------------------------------------------------------------
// Combined gate weights, split into bf16 hi/lo. Rows >= NC are zero.
__global__ void __launch_bounds__(256) k_prep(
        const float* __restrict__ WihS, const float* __restrict__ WhhS,
        const float* __restrict__ bihS, const float* __restrict__ bhhS,
        const float* __restrict__ WihU, const float* __restrict__ WhhU,
        const float* __restrict__ bihU, const float* __restrict__ bhhU) {
    int j = blockIdx.x;
    __nv_bfloat16* wh = g_Wch + (size_t)j * KC;
    __nv_bfloat16* wl = g_Wcl + (size_t)j * KC;
    for (int k = threadIdx.x; k < KC; k += 256) {
        float v = 0.f;
        if (j < G4H) {
            if (k < 906) v = WihS[(size_t)j * 906 + k];
            else if (k < 1531) v = WhhS[(size_t)j * Hv + (k - 906)];
        } else if (j < NC) {
            int jj = j - G4H;
            if (k < 906) v = WihU[(size_t)jj * 906 + k];
            else if (k >= 1531 && k < 1556) v = WhhU[(size_t)jj * Dv + (k - 1531)];
        }
        __nv_bfloat16 h = __float2bfloat16(v);
        wh[k] = h;
        wl[k] = __float2bfloat16(v - __bfloat162float(h));
    }
    if (threadIdx.x == 0 && j < NC) {
        g_bsumC[j] = (j < G4H) ? (bihS[j] + bhhS[j])
                               : (bihU[j - G4H] + bhhU[j - G4H]);
    }
}

// Split fcW (fp32 [V,625]) into hi/lo bf16 [V,640]
__global__ void __launch_bounds__(128) k_split_w(const float* __restrict__ fcW) {
    int row = blockIdx.x;
    const float* src = fcW + (size_t)row * Hv;
    __nv_bfloat16* dh = g_Wh + (size_t)row * FCK;
    __nv_bfloat16* dl = g_Wl + (size_t)row * FCK;
    for (int k = threadIdx.x; k < FCK; k += 128) {
        float x = (k < Hv) ? src[k] : 0.f;
        __nv_bfloat16 h = __float2bfloat16(x);
        dh[k] = h;
        dl[k] = __float2bfloat16(x - __bfloat162float(h));
    }
}

// Split wordOut into hi/lo bf16 [1536,640]
__global__ void __launch_bounds__(128) k_split_a() {
    int row = blockIdx.x;
    const float* src = g_wordOut + (size_t)row * WO_LD;
    __nv_bfloat16* dh = g_Ah + (size_t)row * FCK;
    __nv_bfloat16* dl = g_Al + (size_t)row * FCK;
    for (int k = threadIdx.x; k < FCK; k += 128) {
        float x = (k < Hv) ? src[k] : 0.f;
        __nv_bfloat16 h = __float2bfloat16(x);
        dh[k] = h;
        dl[k] = __float2bfloat16(x - __bfloat162float(h));
    }
}

// ---------------------------------------------------------------------------
__global__ void __launch_bounds__(640) k_init(
        const float* __restrict__ features, const float* __restrict__ embed,
        const float* __restrict__ szW, const float* __restrict__ szb) {
    int b = blockIdx.x;
    int t = threadIdx.x;
    __shared__ float s_f[Ev];
    if (t < Ev) s_f[t] = features[b * Ev + t];
    __syncthreads();
    float* xh = g_xh + b * XH_LD;
    if (t < Hv) {
        float acc = szb[t];
        const float* w = szW + t * Ev;
        #pragma unroll 4
        for (int k = 0; k < Ev; k++) acc += s_f[k] * w[k];
        xh[281 + t] = acc;
        xh[906 + t] = 0.f;
    }
    if (t < Dv) { xh[t] = 0.f; xh[1531 + t] = 0.f; }
    if (t < 12) xh[1556 + t] = 0.f;
    if (t < Ev) xh[25 + t] = embed[t];
    g_wordOut[b * WO_LD + t] = 0.f;
    __syncthreads();   // xh row complete -> build bf16 splits
    for (int k = t; k < XH_LD; k += 640) {
        float x = xh[k];
        __nv_bfloat16 h = __float2bfloat16(x);
        g_xh_h[b * XH_LD + k] = h;
        g_xh_l[b * XH_LD + k] = __float2bfloat16(x - __bfloat162float(h));
    }
}

// ---------------------------------------------------------------------------
// mma.sync helpers
__device__ __forceinline__ uint32_t s2u(const void* p) {
    return (uint32_t)__cvta_generic_to_shared(p);
}
__device__ __forceinline__ void cp16(uint32_t dst, const void* src) {
    asm volatile("cp.async.cg.shared.global [%0], [%1], 16;\n" :: "r"(dst), "l"(src));
}
__device__ __forceinline__ void ldmA(uint32_t* a, uint32_t addr) {
    asm volatile("ldmatrix.sync.aligned.m8n8.x4.shared.b16 {%0,%1,%2,%3}, [%4];"
                 : "=r"(a[0]), "=r"(a[1]), "=r"(a[2]), "=r"(a[3]) : "r"(addr));
}
__device__ __forceinline__ void ldmB(uint32_t* b, uint32_t addr) {
    asm volatile("ldmatrix.sync.aligned.m8n8.x2.shared.b16 {%0,%1}, [%2];"
                 : "=r"(b[0]), "=r"(b[1]) : "r"(addr));
}
__device__ __forceinline__ void mma16816(float* c, const uint32_t* a, const uint32_t* b) {
    asm volatile(
        "mma.sync.aligned.m16n8k16.row.col.f32.bf16.bf16.f32 "
        "{%0,%1,%2,%3}, {%4,%5,%6,%7}, {%8,%9}, {%0,%1,%2,%3};"
        : "+f"(c[0]), "+f"(c[1]), "+f"(c[2]), "+f"(c[3])
        : "r"(a[0]), "r"(a[1]), "r"(a[2]), "r"(a[3]), "r"(b[0]), "r"(b[1]));
}

// ---------------------------------------------------------------------------
// Gate GEMM (bf16 hi/lo fused one-pass, mma.sync, split-K over blockIdx.z)
// A-smem: rows 0-63 xh_h, 64-127 xh_l. B-smem: rows 0-63 Wch, 64-127 Wcl.
// Per k-tile: acc += Ah@Wh + Ah@Wl + Al@Wh.
// grid (42, 1, 7), 256 threads (8 warps, warp = 32Mx16N), 5-stage pipeline.
#define G_LDS 40
#define G_STG 5
#define G_NIT 7           // KSEG / 32
__global__ void __launch_bounds__(256) k_gates() {
    __shared__ __align__(16) __nv_bfloat16 As[G_STG][128][G_LDS];
    __shared__ __align__(16) __nv_bfloat16 Bs[G_STG][128][G_LDS];

    const int tid = threadIdx.x;
    const int wid = tid / 32;
    const int lane = tid % 32;
    const int warp_m = wid / 4;        // 0..1 -> 32 batch rows each
    const int warp_n = wid % 4;        // 0..3 -> 16 gate cols each
    const int n0 = blockIdx.x * 64;
    const int z = blockIdx.z;
    const int kbeg = z * KSEG;

    const __nv_bfloat16* Ahb = g_xh_h + kbeg;
    const __nv_bfloat16* Alb = g_xh_l + kbeg;
    const __nv_bfloat16* Whb = g_Wch + (size_t)n0 * KC + kbeg;
    const __nv_bfloat16* Wlb = g_Wcl + (size_t)n0 * KC + kbeg;

    const int lr = tid >> 2;           // 0..63
    const int lc = tid & 3;            // 16B column group (8 bf16)

    // load k-tile `j` (wrapped) into pipeline stage `stage`
    auto load = [&](int j, int stage) {
        if (j >= G_NIT) j -= G_NIT;    // redundant tail load (keeps waits uniform)
        int ko = j * 32;
        uint32_t sa = s2u(&As[stage][0][0]);
        uint32_t sbb = s2u(&Bs[stage][0][0]);
        uint32_t so = (lr * G_LDS + lc * 8) * 2;
        uint32_t so2 = ((lr + 64) * G_LDS + lc * 8) * 2;
        cp16(sa + so,  Ahb + (size_t)lr * XH_LD + ko + lc * 8);
        cp16(sa + so2, Alb + (size_t)lr * XH_LD + ko + lc * 8);
        cp16(sbb + so,  Whb + (size_t)lr * KC + ko + lc * 8);
        cp16(sbb + so2, Wlb + (size_t)lr * KC + ko + lc * 8);
        asm volatile("cp.async.commit_group;" ::: "memory");
    };

    float acc[2][2][4];
    #pragma unroll
    for (int i = 0; i < 2; i++)
        #pragma unroll
        for (int j = 0; j < 2; j++)
            #pragma unroll
            for (int q = 0; q < 4; q++) acc[i][j][q] = 0.f;

    const int agrp = lane >> 3;
    const int alr = lane & 7;
    const int am_off = (agrp & 1) * 8;
    const int ak_off = (agrp >> 1) * 8;
    const int l16 = lane & 15;
    const int bn_off = l16 & 7;
    const int bk_off = (l16 >> 3) * 8;

    load(0, 0); load(1, 1); load(2, 2); load(3, 3); load(4, 4);

    for (int it = 0; it < G_NIT; it++) {
        int s = it % G_STG;
        asm volatile("cp.async.wait_group 4;" ::: "memory");  // stage `it` complete
        __syncthreads();

        #pragma unroll
        for (int kf = 0; kf < 2; kf++) {
            uint32_t ah[2][4], al[2][4], bh[2][2], bl[2][2];
            #pragma unroll
            for (int mi = 0; mi < 2; mi++) {
                int row = warp_m * 32 + mi * 16 + am_off + alr;
                ldmA(ah[mi], s2u(&As[s][row][kf * 16 + ak_off]));
                ldmA(al[mi], s2u(&As[s][64 + row][kf * 16 + ak_off]));
            }
            #pragma unroll
            for (int nj = 0; nj < 2; nj++) {
                int row = warp_n * 16 + nj * 8 + bn_off;
                ldmB(bh[nj], s2u(&Bs[s][row][kf * 16 + bk_off]));
                ldmB(bl[nj], s2u(&Bs[s][64 + row][kf * 16 + bk_off]));
            }
            #pragma unroll
            for (int mi = 0; mi < 2; mi++)
                #pragma unroll
                for (int nj = 0; nj < 2; nj++) {
                    mma16816(acc[mi][nj], ah[mi], bh[nj]);
                    mma16816(acc[mi][nj], ah[mi], bl[nj]);
                    mma16816(acc[mi][nj], al[mi], bh[nj]);
                }
        }
        __syncthreads();                 // all warps done with stage s
        load(it + G_STG, s);             // refill freed stage (wrapped past end)
    }
    asm volatile("cp.async.wait_group 0;" ::: "memory");  // drain before exit

    // store partials: gP[(b*NCP + n)*8 + z]
    #pragma unroll
    for (int mi = 0; mi < 2; mi++) {
        int gm = warp_m * 32 + mi * 16 + lane / 4;
        #pragma unroll
        for (int nj = 0; nj < 2; nj++) {
            int gn = n0 + warp_n * 16 + nj * 8 + (lane % 4) * 2;
            g_gP[((size_t)gm * NCP + gn) * 8 + z]           = acc[mi][nj][0];
            g_gP[((size_t)gm * NCP + gn + 1) * 8 + z]       = acc[mi][nj][1];
            g_gP[((size_t)(gm + 8) * NCP + gn) * 8 + z]     = acc[mi][nj][2];
            g_gP[((size_t)(gm + 8) * NCP + gn + 1) * 8 + z] = acc[mi][nj][3];
        }
    }
}

__device__ __forceinline__ float sigm(float x) { return 1.f / (1.f + expf(-x)); }
__device__ __forceinline__ float red7(const float* p) {
    float4 u = *(const float4*)p;
    float4 v = *(const float4*)(p + 4);
    return u.x + u.y + u.z + u.w + v.x + v.y + v.z;   // 7 partials, slot 7 unused
}

// ---------------------------------------------------------------------------
__global__ void __launch_bounds__(UPD_T) k_update(
        const float* __restrict__ embed, const int* __restrict__ captions,
        const float* __restrict__ wuW, const float* __restrict__ wub, int step) {
    int b = blockIdx.x;
    int t = threadIdx.x;
    __shared__ float s_x[906];
    __shared__ float s_gU[G4D];
    __shared__ float s_hS[Hv];
    __shared__ float s_hU[Dv];
    __shared__ float s_ut[Hv];
    float* xh = g_xh + b * XH_LD;
    __nv_bfloat16* xhh = g_xh_h + b * XH_LD;
    __nv_bfloat16* xhl = g_xh_l + b * XH_LD;
    for (int k = t; k < 906; k += UPD_T) s_x[k] = xh[k];
    __syncthreads();

    const float* gpb = g_gP + (size_t)b * NCP * 8;
    if (t < Hv) {
        float g0 = g_bsumC[t]            + red7(gpb + (size_t)t * 8);
        float g1 = g_bsumC[Hv + t]       + red7(gpb + (size_t)(Hv + t) * 8);
        float g2 = g_bsumC[2 * Hv + t]   + red7(gpb + (size_t)(2 * Hv + t) * 8);
        float g3 = g_bsumC[3 * Hv + t]   + red7(gpb + (size_t)(3 * Hv + t) * 8);
        float i = sigm(g0), f = sigm(g1), gg = tanhf(g2), o = sigm(g3);
        float c = f * s_x[281 + t] + i * gg;
        float h = o * tanhf(c);
        s_hS[t] = h;
        xh[281 + t] = c;
        xh[906 + t] = h;
        __nv_bfloat16 ch = __float2bfloat16(c);
        xhh[281 + t] = ch;
        xhl[281 + t] = __float2bfloat16(c - __bfloat162float(ch));
        __nv_bfloat16 hh = __float2bfloat16(h);
        xhh[906 + t] = hh;
        xhl[906 + t] = __float2bfloat16(h - __bfloat162float(hh));
    } else if (t < Hv + G4D) {
        int j = t - Hv;
        s_gU[j] = g_bsumC[G4H + j] + red7(gpb + (size_t)(G4H + j) * 8);
    }
    if (step < NSTEP - 1 && t < Ev) {
        int w = captions[b * Tv + step + 1];
        float x = embed[w * Ev + t];
        xh[25 + t] = x;
        __nv_bfloat16 hh = __float2bfloat16(x);
        xhh[25 + t] = hh;
        xhl[25 + t] = __float2bfloat16(x - __bfloat162float(hh));
    }
    __syncthreads();

    if (t < Dv) {
        float i = sigm(s_gU[t]);
        float f = sigm(s_gU[Dv + t]);
        float g = tanhf(s_gU[2 * Dv + t]);
        float o = sigm(s_gU[3 * Dv + t]);
        float c = f * s_x[t] + i * g;
        float h = o * tanhf(c);
        s_hU[t] = h;
        xh[t] = c;
        xh[1531 + t] = h;
        __nv_bfloat16 ch = __float2bfloat16(c);
        xhh[t] = ch;
        xhl[t] = __float2bfloat16(c - __bfloat162float(ch));
        __nv_bfloat16 hh = __float2bfloat16(h);
        xhh[1531 + t] = hh;
        xhl[1531 + t] = __float2bfloat16(h - __bfloat162float(hh));
    }
    __syncthreads();

    if (t < Hv) {
        float acc = wub[t];
        const float* w = wuW + t * Dv;
        #pragma unroll
        for (int k = 0; k < Dv; k++) acc += s_hU[k] * w[k];
        s_ut[t] = acc;
    }
    __syncthreads();

    if (t < Hv) {
        int r = t / Dv, c = t % Dv;
        float acc = 0.f;
        #pragma unroll
        for (int k = 0; k < Dv; k++) acc += s_ut[r * Dv + k] * s_hS[k * Dv + c];
        g_wordOut[(size_t)(step + 1) * (Bv * WO_LD) + b * WO_LD + t] = acc;
    }
}

// ---------------------------------------------------------------------------
// fc GEMM (unchanged from R7)
__global__ void __launch_bounds__(256) k_fc(const float* __restrict__ fcb,
                                            float* __restrict__ out) {
    __shared__ __align__(16) __nv_bfloat16 As[2][128][FC_LDS];
    __shared__ __align__(16) __nv_bfloat16 Bs[2][128][FC_LDS];

    const int tid = threadIdx.x;
    const int wid = tid / 32;
    const int lane = tid % 32;
    const int warp_m = wid / 4;
    const int warp_n = wid % 4;

    int t = blockIdx.x;
    int patch = t / 300, within = t % 300;
    int m0 = (within % 12) * 128;
    int n0 = (patch * 25 + within / 12) * 128;

    const __nv_bfloat16* segA[3] = {
        g_Ah + (size_t)m0 * FCK, g_Ah + (size_t)m0 * FCK, g_Al + (size_t)m0 * FCK };
    const __nv_bfloat16* segW[3] = {
        g_Wh + (size_t)n0 * FCK, g_Wl + (size_t)n0 * FCK, g_Wh + (size_t)n0 * FCK };

    const int lr = tid >> 2;
    const int lc = tid & 3;

    auto load = [&](int it, int stage) {
        int seg = it / FC_NKT, kt = it % FC_NKT;
        const __nv_bfloat16* A = segA[seg] + kt * FC_BK;
        const __nv_bfloat16* W = segW[seg] + kt * FC_BK;
        uint32_t sa = s2u(&As[stage][0][0]);
        uint32_t sbb = s2u(&Bs[stage][0][0]);
        #pragma unroll
        for (int i = 0; i < 2; i++) {
            int r = lr + i * 64;
            uint32_t soff = (r * FC_LDS + lc * 8) * 2;
            cp16(sa + soff, A + (size_t)r * FCK + lc * 8);
            cp16(sbb + soff, W + (size_t)r * FCK + lc * 8);
        }
        asm volatile("cp.async.commit_group;" ::: "memory");
    };

    float acc[4][4][4];
    #pragma unroll
    for (int i = 0; i < 4; i++)
        #pragma unroll
        for (int j = 0; j < 4; j++)
            #pragma unroll
            for (int q = 0; q < 4; q++) acc[i][j][q] = 0.f;

    const int agrp = lane >> 3;
    const int alr = lane & 7;
    const int am_off = (agrp & 1) * 8;
    const int ak_off = (agrp >> 1) * 8;
    const int l16 = lane & 15;
    const int bn_off = l16 & 7;
    const int bk_off = (l16 >> 3) * 8;

    load(0, 0);
    const int NIT = 3 * FC_NKT;
    for (int it = 0; it < NIT; it++) {
        int s = it & 1;
        if (it + 1 < NIT) {
            load(it + 1, s ^ 1);
            asm volatile("cp.async.wait_group 1;" ::: "memory");
        } else {
            asm volatile("cp.async.wait_group 0;" ::: "memory");
        }
        __syncthreads();

        #pragma unroll
        for (int kf = 0; kf < 2; kf++) {
            uint32_t af[4][4], bfr[4][2];
            #pragma unroll
            for (int mi = 0; mi < 4; mi++) {
                int row = warp_m * 64 + mi * 16 + am_off + alr;
                ldmA(af[mi], s2u(&As[s][row][kf * 16 + ak_off]));
            }
            #pragma unroll
            for (int nj = 0; nj < 4; nj++) {
                int row = warp_n * 32 + nj * 8 + bn_off;
                ldmB(bfr[nj], s2u(&Bs[s][row][kf * 16 + bk_off]));
            }
            #pragma unroll
            for (int mi = 0; mi < 4; mi++)
                #pragma unroll
                for (int nj = 0; nj < 4; nj++)
                    mma16816(acc[mi][nj], af[mi], bfr[nj]);
        }
        __syncthreads();
    }

    #pragma unroll
    for (int mi = 0; mi < 4; mi++) {
        int gm = m0 + warp_m * 64 + mi * 16 + lane / 4;
        #pragma unroll
        for (int nj = 0; nj < 4; nj++) {
            int gn = n0 + warp_n * 32 + nj * 8 + (lane % 4) * 2;
            float b0 = fcb[gn], b1 = fcb[gn + 1];
            float2 v0 = make_float2(acc[mi][nj][0] + b0, acc[mi][nj][1] + b1);
            float2 v1 = make_float2(acc[mi][nj][2] + b0, acc[mi][nj][3] + b1);
            *(float2*)(out + (size_t)gm * Vv + gn) = v0;
            *(float2*)(out + (size_t)(gm + 8) * Vv + gn) = v1;
        }
    }
}

// ---------------------------------------------------------------------------
extern "C" void kernel_launch(void* const* d_in, const int* in_sizes, int n_in,
                              void* d_out, int out_size) {
    const float* features = (const float*)d_in[0];
    const int*   captions = (const int*)d_in[1];
    const float* embed    = (const float*)d_in[2];
    const float* WihS     = (const float*)d_in[3];
    const float* WhhS     = (const float*)d_in[4];
    const float* bihS     = (const float*)d_in[5];
    const float* bhhS     = (const float*)d_in[6];
    const float* WihU     = (const float*)d_in[7];
    const float* WhhU     = (const float*)d_in[8];
    const float* bihU     = (const float*)d_in[9];
    const float* bhhU     = (const float*)d_in[10];
    const float* fcW      = (const float*)d_in[11];
    const float* fcb      = (const float*)d_in[12];
    const float* szW      = (const float*)d_in[13];
    const float* szb      = (const float*)d_in[14];
    const float* wuW      = (const float*)d_in[15];
    const float* wub      = (const float*)d_in[16];
    float* out = (float*)d_out;

    k_split_w<<<Vv, 128>>>(fcW);    // big streaming writes first (keep Wc warm in L2)
    k_prep<<<NCP, 256>>>(WihS, WhhS, bihS, bhhS, WihU, WhhU, bihU, bhhU);
    k_init<<<Bv, 640>>>(features, embed, szW, szb);

    for (int s = 0; s < NSTEP; s++) {
        k_gates<<<dim3(NCP / 64, 1, SPLITK), 256>>>();
        k_update<<<Bv, UPD_T>>>(embed, captions, wuW, wub, s);
    }

    k_split_a<<<FCM, 128>>>();
    k_fc<<<(FCM / 128) * (Vv / 128), 256>>>(fcb, out);
}